// round 14
// baseline (speedup 1.0000x reference)
#include <cuda_runtime.h>
#include <cuda_bf16.h>
#include <cuda_fp16.h>
#include <math.h>
#include <stdint.h>
#include <string.h>

// Problem constants
#define Bn 4
#define Sn 2048
#define Dn 1024
#define Hn 16
#define Mn (Bn * Sn)                            // 8192 rows
#define OUT_ELEMS ((size_t)Mn * Dn)             // 8,388,608
#define ATTN_ELEMS ((size_t)Bn * Hn * Sn * Sn)  // 268,435,456
#define NTRI 528                                // 32*33/2 lower-tri blocks

// Scratch (device globals; no allocations allowed)
__device__ float g_ctx[(size_t)Mn * Dn];
__device__ float g_m[Bn * Hn * Sn];
__device__ float g_l[Bn * Hn * Sn];
// fp16 probabilities exp(s - m_run) for lower-tri blocks + per-tile run max
__device__ __align__(16) __half g_P[(size_t)Bn * Hn * NTRI * 4096];
__device__ float g_mr[(size_t)Bn * Hn * NTRI * 64];

// bf16 split inputs for tensor-core projection
__device__ __align__(16) __nv_bfloat16 g_Xhi[(size_t)3 * Mn * Dn];
__device__ __align__(16) __nv_bfloat16 g_Xlo[(size_t)3 * Mn * Dn];
__device__ __align__(16) __nv_bfloat16 g_Whi[(size_t)3 * Dn * Dn];  // [n][k]
__device__ __align__(16) __nv_bfloat16 g_Wlo[(size_t)3 * Dn * Dn];

// bf16 split tensors for flash attention (Q, K) + fp16 transposed V
__device__ __align__(16) __nv_bfloat16 g_Qhi[(size_t)Mn * Dn];  // scaled
__device__ __align__(16) __nv_bfloat16 g_Qlo[(size_t)Mn * Dn];
__device__ __align__(16) __nv_bfloat16 g_Khi[(size_t)Mn * Dn];
__device__ __align__(16) __nv_bfloat16 g_Klo[(size_t)Mn * Dn];
__device__ __align__(16) __half g_Vth[(size_t)Bn * Hn * 64 * Sn];

typedef unsigned long long u64t;

// ---------------------------------------------------------------------------
// helpers
// ---------------------------------------------------------------------------
__device__ __forceinline__ uint32_t cvta_shared(const void* p) {
  uint32_t a;
  asm("{ .reg .u64 t; cvta.to.shared.u64 t, %1; cvt.u32.u64 %0, t; }"
      : "=r"(a) : "l"(p));
  return a;
}
__device__ __forceinline__ void bsplit(float x, unsigned short& hi,
                                       unsigned short& lo) {
  __nv_bfloat16 h = __float2bfloat16_rn(x);
  __nv_bfloat16 l = __float2bfloat16_rn(x - __bfloat162float(h));
  hi = __bfloat16_as_ushort(h);
  lo = __bfloat16_as_ushort(l);
}
// pack pair (x -> low16, y -> high16) as bf16 hi-part and residual lo-part
__device__ __forceinline__ void split_pair(float x, float y, uint32_t& hi,
                                           uint32_t& lo) {
  __nv_bfloat16 xh = __float2bfloat16_rn(x), yh = __float2bfloat16_rn(y);
  float xr = x - __bfloat162float(xh), yr = y - __bfloat162float(yh);
  __nv_bfloat16 xl = __float2bfloat16_rn(xr), yl = __float2bfloat16_rn(yr);
  hi = (uint32_t)__bfloat16_as_ushort(xh) |
       ((uint32_t)__bfloat16_as_ushort(yh) << 16);
  lo = (uint32_t)__bfloat16_as_ushort(xl) |
       ((uint32_t)__bfloat16_as_ushort(yl) << 16);
}

__device__ __forceinline__ void ldmx4(uint32_t* r, uint32_t addr) {
  asm volatile(
      "ldmatrix.sync.aligned.m8n8.x4.shared.b16 {%0,%1,%2,%3}, [%4];"
      : "=r"(r[0]), "=r"(r[1]), "=r"(r[2]), "=r"(r[3])
      : "r"(addr));
}
__device__ __forceinline__ void mma_bf16(float* c, const uint32_t* a,
                                         const uint32_t* b) {
  asm volatile(
      "mma.sync.aligned.m16n8k16.row.col.f32.bf16.bf16.f32 "
      "{%0,%1,%2,%3}, {%4,%5,%6,%7}, {%8,%9}, {%0,%1,%2,%3};"
      : "+f"(c[0]), "+f"(c[1]), "+f"(c[2]), "+f"(c[3])
      : "r"(a[0]), "r"(a[1]), "r"(a[2]), "r"(a[3]), "r"(b[0]), "r"(b[1]));
}
__device__ __forceinline__ void mma_fp16(float* c, const uint32_t* a,
                                         const uint32_t* b) {
  asm volatile(
      "mma.sync.aligned.m16n8k16.row.col.f32.f16.f16.f32 "
      "{%0,%1,%2,%3}, {%4,%5,%6,%7}, {%8,%9}, {%0,%1,%2,%3};"
      : "+f"(c[0]), "+f"(c[1]), "+f"(c[2]), "+f"(c[3])
      : "r"(a[0]), "r"(a[1]), "r"(a[2]), "r"(a[3]), "r"(b[0]), "r"(b[1]));
}
__device__ __forceinline__ void cp16(uint32_t saddr, const void* gaddr) {
  asm volatile("cp.async.cg.shared.global [%0], [%1], 16;" ::"r"(saddr),
               "l"(gaddr));
}
#define CP_COMMIT() asm volatile("cp.async.commit_group;" ::: "memory")
#define CP_WAIT2() asm volatile("cp.async.wait_group 2;" ::: "memory")
#define CP_WAIT1() asm volatile("cp.async.wait_group 1;" ::: "memory")
#define CP_WAIT0() asm volatile("cp.async.wait_group 0;" ::: "memory")

// ---------------------------------------------------------------------------
// Kernel 0: fused input prep. grid (5120, 3), 256 threads.
//   x < 4096: split q/k/v into bf16 hi/lo.
//   x >= 4096: transpose + split W (32x32 tile per block).
// ---------------------------------------------------------------------------
__global__ __launch_bounds__(256) void prep_inputs(
    const float* __restrict__ q, const float* __restrict__ k,
    const float* __restrict__ v, const float* __restrict__ Wq,
    const float* __restrict__ Wk, const float* __restrict__ Wv) {
  const int which = blockIdx.y;
  const int t = threadIdx.x;
  __shared__ float tile[32][33];

  if (blockIdx.x < 4096) {
    const float* X = (which == 0) ? q : (which == 1) ? k : v;
    size_t off = ((size_t)blockIdx.x * 256 + t) * 8;
    float4 a = *(const float4*)(X + off);
    float4 b = *(const float4*)(X + off + 4);
    unsigned short h[8], l[8];
    bsplit(a.x, h[0], l[0]); bsplit(a.y, h[1], l[1]);
    bsplit(a.z, h[2], l[2]); bsplit(a.w, h[3], l[3]);
    bsplit(b.x, h[4], l[4]); bsplit(b.y, h[5], l[5]);
    bsplit(b.z, h[6], l[6]); bsplit(b.w, h[7], l[7]);
    uint4 uh, ul;
    uh.x = (uint32_t)h[0] | ((uint32_t)h[1] << 16);
    uh.y = (uint32_t)h[2] | ((uint32_t)h[3] << 16);
    uh.z = (uint32_t)h[4] | ((uint32_t)h[5] << 16);
    uh.w = (uint32_t)h[6] | ((uint32_t)h[7] << 16);
    ul.x = (uint32_t)l[0] | ((uint32_t)l[1] << 16);
    ul.y = (uint32_t)l[2] | ((uint32_t)l[3] << 16);
    ul.z = (uint32_t)l[4] | ((uint32_t)l[5] << 16);
    ul.w = (uint32_t)l[6] | ((uint32_t)l[7] << 16);
    size_t dst = (size_t)which * Mn * Dn + off;
    *(uint4*)((char*)g_Xhi + dst * 2) = uh;
    *(uint4*)((char*)g_Xlo + dst * 2) = ul;
  } else {
    const float* W = (which == 0) ? Wq : (which == 1) ? Wk : Wv;
    const int bx = blockIdx.x - 4096;
    const int x0 = (bx & 31) * 32, y0 = (bx >> 5) * 32;
    const int tx = t & 31, ty = t >> 5;  // 32 x 8
#pragma unroll
    for (int j = 0; j < 32; j += 8)
      tile[ty + j][tx] = W[(size_t)(y0 + ty + j) * Dn + x0 + tx];
    __syncthreads();
    size_t base = (size_t)which * Dn * Dn;
#pragma unroll
    for (int j = 0; j < 32; j += 8) {
      float x = tile[tx][ty + j];
      unsigned short h, l;
      bsplit(x, h, l);
      size_t dst = base + (size_t)(x0 + ty + j) * Dn + y0 + tx;
      ((unsigned short*)g_Whi)[dst] = h;
      ((unsigned short*)g_Wlo)[dst] = l;
    }
  }
}

// ---------------------------------------------------------------------------
// Kernel 1: QKV projection via mma.sync bf16 (4-stage pipeline).
// Epilogue fused: which=0 -> Qhi/Qlo (scaled 0.125), which=1 -> Khi/Klo,
// which=2 -> TRANSPOSED fp16 V (g_Vth) via smem staging.
// ---------------------------------------------------------------------------
#define LDB3 48               // bytes per smem row (16 bf16 + pad)
#define ARR3 (128 * LDB3)     // 6144
#define STAGE3 (4 * ARR3)     // 24576
#define PROJ_SMEM (4 * STAGE3)  // 98304
#define VSTR 136              // fp16 stride for Vt staging (pad vs banks)
__global__ __launch_bounds__(256, 2) void proj_mma() {
  extern __shared__ char smc[];
  const uint32_t smem_base = cvta_shared(smc);

  const int which = blockIdx.z;
  const __nv_bfloat16* Xhi = g_Xhi + (size_t)which * Mn * Dn;
  const __nv_bfloat16* Xlo = g_Xlo + (size_t)which * Mn * Dn;
  const __nv_bfloat16* Whi = g_Whi + (size_t)which * Dn * Dn;
  const __nv_bfloat16* Wlo = g_Wlo + (size_t)which * Dn * Dn;

  const int t = threadIdx.x;
  const int lane = t & 31, w = t >> 5;
  const int m0 = blockIdx.y * 128, n0 = blockIdx.x * 128;
  const int m_warp = (w & 1) * 64, n_warp = (w >> 1) * 32;

  const int arr = t >> 6, u = t & 63;
  const __nv_bfloat16* gsrc =
      (arr == 0) ? Xhi : (arr == 1) ? Xlo : (arr == 2) ? Whi : Wlo;
  const int grow0 = (arr < 2) ? m0 : n0;

  auto issue_stage = [&](int kc, int buf) {
    uint32_t sbase = smem_base + buf * STAGE3 + arr * ARR3;
    const int k0 = kc * 16;
#pragma unroll
    for (int j = 0; j < 4; j++) {
      int c = u * 4 + j;
      int row = c >> 1, ch = c & 1;
      cp16(sbase + row * LDB3 + ch * 16,
           gsrc + (size_t)(grow0 + row) * Dn + k0 + ch * 8);
    }
    CP_COMMIT();
  };

  float acc[4][4][4];
#pragma unroll
  for (int i = 0; i < 4; i++)
#pragma unroll
    for (int j = 0; j < 4; j++)
#pragma unroll
      for (int r = 0; r < 4; r++) acc[i][j][r] = 0.f;

  issue_stage(0, 0);
  issue_stage(1, 1);
  issue_stage(2, 2);

  const uint32_t a_off = (lane & 15) * LDB3 + ((lane >> 4) << 4);
  const uint32_t b_off =
      ((lane & 7) + ((lane >> 4) << 3)) * LDB3 + (((lane >> 3) & 1) << 4);

  for (int kc = 0; kc < 64; kc++) {
    if (kc < 62) { CP_WAIT2(); } else if (kc < 63) { CP_WAIT1(); } else {
      CP_WAIT0();
    }
    __syncthreads();
    const uint32_t sA = smem_base + (kc & 3) * STAGE3;
    const uint32_t sAl = sA + ARR3;
    const uint32_t sBh = sA + 2 * ARR3;
    const uint32_t sBl = sA + 3 * ARR3;

    uint32_t ahi[4][4], alo[4][4];
#pragma unroll
    for (int mf = 0; mf < 4; mf++) {
      uint32_t ro = (m_warp + mf * 16) * LDB3 + a_off;
      ldmx4(ahi[mf], sA + ro);
      ldmx4(alo[mf], sAl + ro);
    }
    uint32_t bh[4][2], bl[4][2];
#pragma unroll
    for (int ng = 0; ng < 2; ng++) {
      uint32_t ro = (n_warp + ng * 16) * LDB3 + b_off;
      uint32_t r4[4];
      ldmx4(r4, sBh + ro);
      bh[2 * ng][0] = r4[0]; bh[2 * ng][1] = r4[1];
      bh[2 * ng + 1][0] = r4[2]; bh[2 * ng + 1][1] = r4[3];
      ldmx4(r4, sBl + ro);
      bl[2 * ng][0] = r4[0]; bl[2 * ng][1] = r4[1];
      bl[2 * ng + 1][0] = r4[2]; bl[2 * ng + 1][1] = r4[3];
    }
#pragma unroll
    for (int mf = 0; mf < 4; mf++)
#pragma unroll
      for (int nf = 0; nf < 4; nf++) {
        mma_bf16(acc[mf][nf], ahi[mf], bh[nf]);
        mma_bf16(acc[mf][nf], ahi[mf], bl[nf]);
        mma_bf16(acc[mf][nf], alo[mf], bh[nf]);
      }
    if (kc + 3 < 64) issue_stage(kc + 3, (kc + 3) & 3);
  }

  const int r0 = lane >> 2, cc = (lane & 3) * 2;
  if (which == 2) {
    // ---- stage V^T (fp16) into smem: vt[n_local][m_local], stride VSTR ----
    __half* vt = (__half*)smc;
#pragma unroll
    for (int mf = 0; mf < 4; mf++) {
      int ml = m_warp + mf * 16 + r0;
#pragma unroll
      for (int nf = 0; nf < 4; nf++) {
        int nl = n_warp + nf * 8 + cc;
        vt[(size_t)nl * VSTR + ml] = __float2half_rn(acc[mf][nf][0]);
        vt[(size_t)(nl + 1) * VSTR + ml] = __float2half_rn(acc[mf][nf][1]);
        vt[(size_t)nl * VSTR + ml + 8] = __float2half_rn(acc[mf][nf][2]);
        vt[(size_t)(nl + 1) * VSTR + ml + 8] = __float2half_rn(acc[mf][nf][3]);
      }
    }
    __syncthreads();
    // ---- coalesced write-out: thread t covers half a d-row (64 fp16) ----
    const int nl = t >> 1, half = t & 1;
    const int b = m0 >> 11;          // batch
    const int s0 = (m0 & 2047) + half * 64;
    const int h = (n0 + nl) >> 6, d = (n0 + nl) & 63;
    __half* dst = g_Vth + ((size_t)(b * Hn + h) * 64 + d) * Sn + s0;
    const __half* src = vt + (size_t)nl * VSTR + half * 64;
#pragma unroll
    for (int j = 0; j < 8; j++)
      *(uint4*)((char*)dst + j * 16) = *(const uint4*)((const char*)src + j * 16);
  } else {
    __nv_bfloat16* Dh = (which == 0) ? g_Qhi : g_Khi;
    __nv_bfloat16* Dl = (which == 0) ? g_Qlo : g_Klo;
    const float sc = (which == 0) ? 0.125f : 1.0f;
#pragma unroll
    for (int mf = 0; mf < 4; mf++) {
      int row = m0 + m_warp + mf * 16 + r0;
#pragma unroll
      for (int nf = 0; nf < 4; nf++) {
        int col = n0 + n_warp + nf * 8 + cc;
        uint32_t hi, lo;
        split_pair(acc[mf][nf][0] * sc, acc[mf][nf][1] * sc, hi, lo);
        *(uint32_t*)((char*)Dh + ((size_t)row * Dn + col) * 2) = hi;
        *(uint32_t*)((char*)Dl + ((size_t)row * Dn + col) * 2) = lo;
        split_pair(acc[mf][nf][2] * sc, acc[mf][nf][3] * sc, hi, lo);
        *(uint32_t*)((char*)Dh + ((size_t)(row + 8) * Dn + col) * 2) = hi;
        *(uint32_t*)((char*)Dl + ((size_t)(row + 8) * Dn + col) * 2) = lo;
      }
    }
  }
}

// ---------------------------------------------------------------------------
// Kernel 2: flash attention (R10 version). QK^T via bf16 3-MMA split; PV via
// fp16 single MMA. grid = (32, 16, 4), 128 threads = 4 warps; LPT.
// ---------------------------------------------------------------------------
#define LDF 144
#define FARR (64 * LDF)       // 9216
#define FSTAGE (3 * FARR)     // 27648
#define FLASH_SMEM (2 * FARR + 2 * FSTAGE)  // 73728
__global__ __launch_bounds__(128, 2) void flash_tc() {
  extern __shared__ char smf[];
  const uint32_t sb = cvta_shared(smf);
  const int qb = 31 - blockIdx.x;  // LPT: longest first
  const int h = blockIdx.y, b = blockIdx.z;
  const int bh = b * Hn + h;
  const int t = threadIdx.x, lane = t & 31, w = t >> 5;

  // ---- load Q hi/lo into smem (plain loads) ----
  {
    int r = t >> 1, c32 = (t & 1) * 32;  // row, 32-bf16 half
    size_t src = ((size_t)(b * Sn + qb * 64 + r)) * Dn + h * 64 + c32;
    uint4 q0 = *(const uint4*)((const char*)g_Qhi + src * 2);
    uint4 q1 = *(const uint4*)((const char*)g_Qhi + src * 2 + 16);
    uint4 q2 = *(const uint4*)((const char*)g_Qhi + src * 2 + 32);
    uint4 q3 = *(const uint4*)((const char*)g_Qhi + src * 2 + 48);
    char* dstH = smf + r * LDF + c32 * 2;
    *(uint4*)dstH = q0; *(uint4*)(dstH + 16) = q1;
    *(uint4*)(dstH + 32) = q2; *(uint4*)(dstH + 48) = q3;
    q0 = *(const uint4*)((const char*)g_Qlo + src * 2);
    q1 = *(const uint4*)((const char*)g_Qlo + src * 2 + 16);
    q2 = *(const uint4*)((const char*)g_Qlo + src * 2 + 32);
    q3 = *(const uint4*)((const char*)g_Qlo + src * 2 + 48);
    char* dstL = smf + FARR + r * LDF + c32 * 2;
    *(uint4*)dstL = q0; *(uint4*)(dstL + 16) = q1;
    *(uint4*)(dstL + 32) = q2; *(uint4*)(dstL + 48) = q3;
  }

  // cp.async stage loader: warps 0,1 -> K hi/lo; warps 2,3 -> half of Vt each
  auto issue_kv = [&](int kb2, int buf) {
    uint32_t stage = sb + 2 * FARR + buf * FSTAGE;
    if (w < 2) {
      const __nv_bfloat16* src = (w == 0) ? g_Khi : g_Klo;
      size_t base = ((size_t)(b * Sn + kb2 * 64)) * Dn + h * 64;
      uint32_t sbase = stage + w * FARR;
#pragma unroll
      for (int j = 0; j < 16; j++) {
        int idx = lane + j * 32;
        int row = idx >> 3, ch = idx & 7;
        cp16(sbase + row * LDF + ch * 16, src + base + row * Dn + ch * 8);
      }
    } else {
      uint32_t sbase = stage + 2 * FARR;
      size_t base = (size_t)bh * 64 * Sn + kb2 * 64;
      const int half = w - 2;
#pragma unroll
      for (int j = 0; j < 8; j++) {
        int idx = lane + j * 32 + half * 256;
        int row = idx >> 3, ch = idx & 7;
        cp16(sbase + row * LDF + ch * 16, g_Vth + base + row * Sn + ch * 8);
      }
    }
    CP_COMMIT();
  };

  issue_kv(0, 0);
  if (qb >= 1) issue_kv(1, 1);

  const int r0 = lane >> 2, cq = (lane & 3) * 2;
  const uint32_t a_off = (lane & 15) * LDF + ((lane >> 4) << 4);
  const uint32_t b_off =
      ((lane & 7) + ((lane >> 4) << 3)) * LDF + (((lane >> 3) & 1) << 4);

  // ---- hoist loop-invariant Q fragments to registers ----
  __syncthreads();  // Q smem visible to all warps
  uint32_t qh[4][4], ql[4][4];
#pragma unroll
  for (int ks = 0; ks < 4; ks++) {
    ldmx4(qh[ks], sb + (w * 16) * LDF + ks * 32 + a_off);
    ldmx4(ql[ks], sb + FARR + (w * 16) * LDF + ks * 32 + a_off);
  }

  float m0 = -1e30f, m1 = -1e30f, l0 = 0.f, l1 = 0.f;
  float O[8][4];
#pragma unroll
  for (int i = 0; i < 8; i++)
#pragma unroll
    for (int j = 0; j < 4; j++) O[i][j] = 0.f;

  const int ig0 = qb * 64 + w * 16 + r0, ig1 = ig0 + 8;

  for (int kb = 0; kb <= qb; kb++) {
    if (kb < qb) { CP_WAIT1(); } else { CP_WAIT0(); }
    __syncthreads();
    const uint32_t st = sb + 2 * FARR + (kb & 1) * FSTAGE;
    const uint32_t sKh = st, sKl = st + FARR;
    const uint32_t sVt = st + 2 * FARR;

    // ---- S = Qs @ K^T (3-MMA bf16 split) ----
    float sc[8][4];
#pragma unroll
    for (int i = 0; i < 8; i++)
#pragma unroll
      for (int j = 0; j < 4; j++) sc[i][j] = 0.f;
#pragma unroll
    for (int ks = 0; ks < 4; ks++) {
#pragma unroll
      for (int ng = 0; ng < 4; ng++) {
        uint32_t kh4[4], kl4[4];
        ldmx4(kh4, sKh + (ng * 16) * LDF + ks * 32 + b_off);
        ldmx4(kl4, sKl + (ng * 16) * LDF + ks * 32 + b_off);
        mma_bf16(sc[2 * ng], qh[ks], kh4);
        mma_bf16(sc[2 * ng], qh[ks], kl4);
        mma_bf16(sc[2 * ng], ql[ks], kh4);
        mma_bf16(sc[2 * ng + 1], qh[ks], kh4 + 2);
        mma_bf16(sc[2 * ng + 1], qh[ks], kl4 + 2);
        mma_bf16(sc[2 * ng + 1], ql[ks], kh4 + 2);
      }
    }

    // ---- causal mask on diag tile ----
    if (kb == qb) {
#pragma unroll
      for (int nf = 0; nf < 8; nf++) {
        int jg = kb * 64 + nf * 8 + cq;
        if (jg > ig0) sc[nf][0] = -1e30f;
        if (jg + 1 > ig0) sc[nf][1] = -1e30f;
        if (jg > ig1) sc[nf][2] = -1e30f;
        if (jg + 1 > ig1) sc[nf][3] = -1e30f;
      }
    }

    // ---- online softmax (registers only) ----
    float mx0 = -1e30f, mx1 = -1e30f;
#pragma unroll
    for (int nf = 0; nf < 8; nf++) {
      mx0 = fmaxf(mx0, fmaxf(sc[nf][0], sc[nf][1]));
      mx1 = fmaxf(mx1, fmaxf(sc[nf][2], sc[nf][3]));
    }
    mx0 = fmaxf(mx0, __shfl_xor_sync(0xffffffffu, mx0, 1));
    mx0 = fmaxf(mx0, __shfl_xor_sync(0xffffffffu, mx0, 2));
    mx1 = fmaxf(mx1, __shfl_xor_sync(0xffffffffu, mx1, 1));
    mx1 = fmaxf(mx1, __shfl_xor_sync(0xffffffffu, mx1, 2));
    float mn0 = fmaxf(m0, mx0), mn1 = fmaxf(m1, mx1);
    float al0 = __expf(m0 - mn0), al1 = __expf(m1 - mn1);

    const size_t tri = (size_t)bh * NTRI + (size_t)(qb * (qb + 1) / 2) + kb;
    if ((lane & 3) == 0) {
      g_mr[tri * 64 + w * 16 + r0] = mn0;
      g_mr[tri * 64 + w * 16 + r0 + 8] = mn1;
    }
    __half* Pt = g_P + tri * 4096;

    float rs0 = 0.f, rs1 = 0.f;
    uint32_t pa[4][4];  // fp16 A-fragments for PV (same bits as stored P)
#pragma unroll
    for (int nf = 0; nf < 8; nf++) {
      float p0 = __expf(sc[nf][0] - mn0);
      float p1 = __expf(sc[nf][1] - mn0);
      float p2 = __expf(sc[nf][2] - mn1);
      float p3 = __expf(sc[nf][3] - mn1);
      rs0 += p0 + p1;
      rs1 += p2 + p3;
      __half2 h01 = __float22half2_rn(make_float2(p0, p1));
      __half2 h23 = __float22half2_rn(make_float2(p2, p3));
      int colb = nf * 8 + cq;
      __stcs((__half2*)(Pt + (w * 16 + r0) * 64 + colb), h01);
      __stcs((__half2*)(Pt + (w * 16 + r0 + 8) * 64 + colb), h23);
      uint32_t u01, u23;
      memcpy(&u01, &h01, 4);
      memcpy(&u23, &h23, 4);
      int kc = nf >> 1, half = nf & 1;
      pa[kc][half * 2 + 0] = u01;
      pa[kc][half * 2 + 1] = u23;
    }
    rs0 += __shfl_xor_sync(0xffffffffu, rs0, 1);
    rs0 += __shfl_xor_sync(0xffffffffu, rs0, 2);
    rs1 += __shfl_xor_sync(0xffffffffu, rs1, 1);
    rs1 += __shfl_xor_sync(0xffffffffu, rs1, 2);
    l0 = l0 * al0 + rs0;
    l1 = l1 * al1 + rs1;
    m0 = mn0;
    m1 = mn1;
#pragma unroll
    for (int nf = 0; nf < 8; nf++) {
      O[nf][0] *= al0; O[nf][1] *= al0;
      O[nf][2] *= al1; O[nf][3] *= al1;
    }

    // ---- O += P @ V (single fp16 MMA; B = Vt fp16) ----
#pragma unroll
    for (int kc = 0; kc < 4; kc++) {
#pragma unroll
      for (int ng = 0; ng < 4; ng++) {
        uint32_t v4[4];
        ldmx4(v4, sVt + (ng * 16) * LDF + kc * 32 + b_off);
        mma_fp16(O[2 * ng], pa[kc], v4);
        mma_fp16(O[2 * ng + 1], pa[kc], v4 + 2);
      }
    }
    __syncthreads();
    if (kb + 2 <= qb) issue_kv(kb + 2, kb & 1);
  }

  // ---- epilogue ----
  const float i0 = 1.0f / l0, i1 = 1.0f / l1;
  float* Cg = g_ctx + ((size_t)(b * Sn + qb * 64)) * Dn + h * 64;
#pragma unroll
  for (int nf = 0; nf < 8; nf++) {
    int colb = nf * 8 + cq;
    *(float2*)(Cg + (size_t)(w * 16 + r0) * Dn + colb) =
        make_float2(O[nf][0] * i0, O[nf][1] * i0);
    *(float2*)(Cg + (size_t)(w * 16 + r0 + 8) * Dn + colb) =
        make_float2(O[nf][2] * i1, O[nf][3] * i1);
  }
  if ((lane & 3) == 0) {
    int base = bh * Sn + qb * 64 + w * 16 + r0;
    g_m[base] = m0; g_l[base] = l0;
    g_m[base + 8] = m1; g_l[base + 8] = l1;
  }
}

// ---------------------------------------------------------------------------
// Kernel 3: attn materialization, row-band streaming version.
// grid = (32 qb, 64 bh), 256 threads. Thread owns quarter-row; loads m/l
// ONCE, then streams all 32 kb tiles (P via __ldcs, stores __stcs).
// ---------------------------------------------------------------------------
__global__ __launch_bounds__(256) void attn_write_fast(
    float* __restrict__ attn) {
  const int qb = blockIdx.x, bh = blockIdx.y;
  const int t = threadIdx.x;
  const int row = t >> 2, c16 = (t & 3) << 4;
  float* dst0 = attn + ((size_t)bh * Sn + qb * 64 + row) * Sn + c16;

  const int rbase = bh * Sn + qb * 64 + row;
  const float mf = g_m[rbase];
  const float inv = 1.0f / g_l[rbase];
  const size_t tri0 = (size_t)bh * NTRI + (size_t)(qb * (qb + 1) / 2);
  const float* mr = g_mr + tri0 * 64 + row;
  const __half2* P0 = (const __half2*)(g_P + tri0 * 4096 + row * 64 + c16);

  for (int kb = 0; kb <= qb; kb++) {
    const float scale = __expf(__ldca(mr + (size_t)kb * 64) - mf) * inv;
    const __half2* Pt = P0 + (size_t)kb * 2048;  // 4096 halfs = 2048 half2
    float* dst = dst0 + kb * 64;
#pragma unroll
    for (int j = 0; j < 4; j++) {
      __half2 a = __ldcs(Pt + 2 * j);
      __half2 c = __ldcs(Pt + 2 * j + 1);
      float2 f0 = __half22float2(a);
      float2 f1 = __half22float2(c);
      __stcs((float4*)(dst + 4 * j),
             make_float4(f0.x * scale, f0.y * scale, f1.x * scale,
                         f1.y * scale));
    }
  }
  const float4 z = make_float4(0.f, 0.f, 0.f, 0.f);
  for (int kb = qb + 1; kb < 32; kb++) {
    float* dst = dst0 + kb * 64;
#pragma unroll
    for (int j = 0; j < 4; j++) __stcs((float4*)(dst + 4 * j), z);
  }
}

// ---------------------------------------------------------------------------
// Kernel 4: residual add + LayerNorm.  grid = 8192 rows, 256 threads.
// ---------------------------------------------------------------------------
__global__ __launch_bounds__(256) void ln_kernel(
    const float* __restrict__ res, const float* __restrict__ gamma,
    const float* __restrict__ beta, float* __restrict__ out) {
  const int row = blockIdx.x;
  const int t = threadIdx.x;
  const float4 cv = ((const float4*)(g_ctx + (size_t)row * Dn))[t];
  const float4 rv = ((const float4*)(res + (size_t)row * Dn))[t];
  float x0 = cv.x + rv.x, x1 = cv.y + rv.y, x2 = cv.z + rv.z, x3 = cv.w + rv.w;

  float sum = x0 + x1 + x2 + x3;
  float sq = x0 * x0 + x1 * x1 + x2 * x2 + x3 * x3;
#pragma unroll
  for (int off = 16; off > 0; off >>= 1) {
    sum += __shfl_xor_sync(0xffffffffu, sum, off);
    sq += __shfl_xor_sync(0xffffffffu, sq, off);
  }
  __shared__ float ssum[8], ssq[8];
  const int w = t >> 5, lane = t & 31;
  if (lane == 0) { ssum[w] = sum; ssq[w] = sq; }
  __syncthreads();
  if (w == 0) {
    float a = (lane < 8) ? ssum[lane] : 0.f;
    float b2 = (lane < 8) ? ssq[lane] : 0.f;
#pragma unroll
    for (int off = 4; off > 0; off >>= 1) {
      a += __shfl_xor_sync(0xffffffffu, a, off);
      b2 += __shfl_xor_sync(0xffffffffu, b2, off);
    }
    if (lane == 0) { ssum[0] = a; ssq[0] = b2; }
  }
  __syncthreads();
  const float mean = ssum[0] * (1.0f / 1024.0f);
  const float var = ssq[0] * (1.0f / 1024.0f) - mean * mean;
  const float rstd = rsqrtf(var + 1e-5f);

  const float4 g = ((const float4*)gamma)[t];
  const float4 be = ((const float4*)beta)[t];
  float4 o = make_float4((x0 - mean) * rstd * g.x + be.x,
                         (x1 - mean) * rstd * g.y + be.y,
                         (x2 - mean) * rstd * g.z + be.z,
                         (x3 - mean) * rstd * g.w + be.w);
  ((float4*)(out + (size_t)row * Dn))[t] = o;
}

// ---------------------------------------------------------------------------
// Inputs (metadata order): q, k, v, mask, Wq, Wk, Wv, ln_gamma, ln_beta
// Output: concat(out[B,S,D], attn[B,H,S,S]) as float32.
// ---------------------------------------------------------------------------
extern "C" void kernel_launch(void* const* d_in, const int* in_sizes, int n_in,
                              void* d_out, int out_size) {
  const float* q = (const float*)d_in[0];
  const float* k = (const float*)d_in[1];
  const float* v = (const float*)d_in[2];
  // d_in[3] = mask (int32) — causal tril, applied analytically
  const float* Wq = (const float*)d_in[4];
  const float* Wk = (const float*)d_in[5];
  const float* Wv = (const float*)d_in[6];
  const float* gamma = (const float*)d_in[7];
  const float* beta = (const float*)d_in[8];
  float* out = (float*)d_out;

  cudaFuncSetAttribute(proj_mma, cudaFuncAttributeMaxDynamicSharedMemorySize,
                       PROJ_SMEM);
  cudaFuncSetAttribute(flash_tc, cudaFuncAttributeMaxDynamicSharedMemorySize,
                       FLASH_SMEM);

  prep_inputs<<<dim3(5120, 3), 256>>>(q, k, v, Wq, Wk, Wv);
  proj_mma<<<dim3(8, 64, 3), 256, PROJ_SMEM>>>();
  flash_tc<<<dim3(32, 16, 4), 128, FLASH_SMEM>>>();
  if ((size_t)out_size >= OUT_ELEMS + ATTN_ELEMS) {
    attn_write_fast<<<dim3(32, 64), 256>>>(out + OUT_ELEMS);
  }
  ln_kernel<<<Mn, 256>>>(q, gamma, beta, out);
}

// round 15
// speedup vs baseline: 1.0339x; 1.0339x over previous
#include <cuda_runtime.h>
#include <cuda_bf16.h>
#include <cuda_fp16.h>
#include <math.h>
#include <stdint.h>
#include <string.h>

// Problem constants
#define Bn 4
#define Sn 2048
#define Dn 1024
#define Hn 16
#define Mn (Bn * Sn)                            // 8192 rows
#define OUT_ELEMS ((size_t)Mn * Dn)             // 8,388,608
#define ATTN_ELEMS ((size_t)Bn * Hn * Sn * Sn)  // 268,435,456
#define NTRI 528                                // 32*33/2 lower-tri blocks

// Scratch (device globals; no allocations allowed)
__device__ float g_ctx[(size_t)Mn * Dn];
__device__ float g_m[Bn * Hn * Sn];
__device__ float g_l[Bn * Hn * Sn];
// fp16 probabilities exp(s - m_run) for lower-tri blocks + per-tile run max
__device__ __align__(16) __half g_P[(size_t)Bn * Hn * NTRI * 4096];
__device__ float g_mr[(size_t)Bn * Hn * NTRI * 64];

// bf16 split inputs for tensor-core projection
__device__ __align__(16) __nv_bfloat16 g_Xhi[(size_t)3 * Mn * Dn];
__device__ __align__(16) __nv_bfloat16 g_Xlo[(size_t)3 * Mn * Dn];
__device__ __align__(16) __nv_bfloat16 g_Whi[(size_t)3 * Dn * Dn];  // [n][k]
__device__ __align__(16) __nv_bfloat16 g_Wlo[(size_t)3 * Dn * Dn];

// bf16 split tensors for flash attention (Q, K) + fp16 transposed V
__device__ __align__(16) __nv_bfloat16 g_Qhi[(size_t)Mn * Dn];  // scaled
__device__ __align__(16) __nv_bfloat16 g_Qlo[(size_t)Mn * Dn];
__device__ __align__(16) __nv_bfloat16 g_Khi[(size_t)Mn * Dn];
__device__ __align__(16) __nv_bfloat16 g_Klo[(size_t)Mn * Dn];
__device__ __align__(16) __half g_Vth[(size_t)Bn * Hn * 64 * Sn];

typedef unsigned long long u64t;

// ---------------------------------------------------------------------------
// helpers
// ---------------------------------------------------------------------------
__device__ __forceinline__ uint32_t cvta_shared(const void* p) {
  uint32_t a;
  asm("{ .reg .u64 t; cvta.to.shared.u64 t, %1; cvt.u32.u64 %0, t; }"
      : "=r"(a) : "l"(p));
  return a;
}
__device__ __forceinline__ void bsplit(float x, unsigned short& hi,
                                       unsigned short& lo) {
  __nv_bfloat16 h = __float2bfloat16_rn(x);
  __nv_bfloat16 l = __float2bfloat16_rn(x - __bfloat162float(h));
  hi = __bfloat16_as_ushort(h);
  lo = __bfloat16_as_ushort(l);
}
// pack pair (x -> low16, y -> high16) as bf16 hi-part and residual lo-part
__device__ __forceinline__ void split_pair(float x, float y, uint32_t& hi,
                                           uint32_t& lo) {
  __nv_bfloat16 xh = __float2bfloat16_rn(x), yh = __float2bfloat16_rn(y);
  float xr = x - __bfloat162float(xh), yr = y - __bfloat162float(yh);
  __nv_bfloat16 xl = __float2bfloat16_rn(xr), yl = __float2bfloat16_rn(yr);
  hi = (uint32_t)__bfloat16_as_ushort(xh) |
       ((uint32_t)__bfloat16_as_ushort(yh) << 16);
  lo = (uint32_t)__bfloat16_as_ushort(xl) |
       ((uint32_t)__bfloat16_as_ushort(yl) << 16);
}

__device__ __forceinline__ void ldmx4(uint32_t* r, uint32_t addr) {
  asm volatile(
      "ldmatrix.sync.aligned.m8n8.x4.shared.b16 {%0,%1,%2,%3}, [%4];"
      : "=r"(r[0]), "=r"(r[1]), "=r"(r[2]), "=r"(r[3])
      : "r"(addr));
}
__device__ __forceinline__ void mma_bf16(float* c, const uint32_t* a,
                                         const uint32_t* b) {
  asm volatile(
      "mma.sync.aligned.m16n8k16.row.col.f32.bf16.bf16.f32 "
      "{%0,%1,%2,%3}, {%4,%5,%6,%7}, {%8,%9}, {%0,%1,%2,%3};"
      : "+f"(c[0]), "+f"(c[1]), "+f"(c[2]), "+f"(c[3])
      : "r"(a[0]), "r"(a[1]), "r"(a[2]), "r"(a[3]), "r"(b[0]), "r"(b[1]));
}
__device__ __forceinline__ void mma_fp16(float* c, const uint32_t* a,
                                         const uint32_t* b) {
  asm volatile(
      "mma.sync.aligned.m16n8k16.row.col.f32.f16.f16.f32 "
      "{%0,%1,%2,%3}, {%4,%5,%6,%7}, {%8,%9}, {%0,%1,%2,%3};"
      : "+f"(c[0]), "+f"(c[1]), "+f"(c[2]), "+f"(c[3])
      : "r"(a[0]), "r"(a[1]), "r"(a[2]), "r"(a[3]), "r"(b[0]), "r"(b[1]));
}
__device__ __forceinline__ void cp16(uint32_t saddr, const void* gaddr) {
  asm volatile("cp.async.cg.shared.global [%0], [%1], 16;" ::"r"(saddr),
               "l"(gaddr));
}
#define CP_COMMIT() asm volatile("cp.async.commit_group;" ::: "memory")
#define CP_WAIT2() asm volatile("cp.async.wait_group 2;" ::: "memory")
#define CP_WAIT1() asm volatile("cp.async.wait_group 1;" ::: "memory")
#define CP_WAIT0() asm volatile("cp.async.wait_group 0;" ::: "memory")

// ---------------------------------------------------------------------------
// Kernel 0: fused input prep. grid (5120, 3), 256 threads.
//   x < 4096: split q/k/v into bf16 hi/lo.
//   x >= 4096: transpose + split W (32x32 tile per block).
// ---------------------------------------------------------------------------
__global__ __launch_bounds__(256) void prep_inputs(
    const float* __restrict__ q, const float* __restrict__ k,
    const float* __restrict__ v, const float* __restrict__ Wq,
    const float* __restrict__ Wk, const float* __restrict__ Wv) {
  const int which = blockIdx.y;
  const int t = threadIdx.x;
  __shared__ float tile[32][33];

  if (blockIdx.x < 4096) {
    const float* X = (which == 0) ? q : (which == 1) ? k : v;
    size_t off = ((size_t)blockIdx.x * 256 + t) * 8;
    float4 a = *(const float4*)(X + off);
    float4 b = *(const float4*)(X + off + 4);
    unsigned short h[8], l[8];
    bsplit(a.x, h[0], l[0]); bsplit(a.y, h[1], l[1]);
    bsplit(a.z, h[2], l[2]); bsplit(a.w, h[3], l[3]);
    bsplit(b.x, h[4], l[4]); bsplit(b.y, h[5], l[5]);
    bsplit(b.z, h[6], l[6]); bsplit(b.w, h[7], l[7]);
    uint4 uh, ul;
    uh.x = (uint32_t)h[0] | ((uint32_t)h[1] << 16);
    uh.y = (uint32_t)h[2] | ((uint32_t)h[3] << 16);
    uh.z = (uint32_t)h[4] | ((uint32_t)h[5] << 16);
    uh.w = (uint32_t)h[6] | ((uint32_t)h[7] << 16);
    ul.x = (uint32_t)l[0] | ((uint32_t)l[1] << 16);
    ul.y = (uint32_t)l[2] | ((uint32_t)l[3] << 16);
    ul.z = (uint32_t)l[4] | ((uint32_t)l[5] << 16);
    ul.w = (uint32_t)l[6] | ((uint32_t)l[7] << 16);
    size_t dst = (size_t)which * Mn * Dn + off;
    *(uint4*)((char*)g_Xhi + dst * 2) = uh;
    *(uint4*)((char*)g_Xlo + dst * 2) = ul;
  } else {
    const float* W = (which == 0) ? Wq : (which == 1) ? Wk : Wv;
    const int bx = blockIdx.x - 4096;
    const int x0 = (bx & 31) * 32, y0 = (bx >> 5) * 32;
    const int tx = t & 31, ty = t >> 5;  // 32 x 8
#pragma unroll
    for (int j = 0; j < 32; j += 8)
      tile[ty + j][tx] = W[(size_t)(y0 + ty + j) * Dn + x0 + tx];
    __syncthreads();
    size_t base = (size_t)which * Dn * Dn;
#pragma unroll
    for (int j = 0; j < 32; j += 8) {
      float x = tile[tx][ty + j];
      unsigned short h, l;
      bsplit(x, h, l);
      size_t dst = base + (size_t)(x0 + ty + j) * Dn + y0 + tx;
      ((unsigned short*)g_Whi)[dst] = h;
      ((unsigned short*)g_Wlo)[dst] = l;
    }
  }
}

// ---------------------------------------------------------------------------
// Kernel 1: QKV projection via mma.sync bf16 (4-stage pipeline).
// Epilogue fused: which=0 -> Qhi/Qlo (scaled 0.125), which=1 -> Khi/Klo,
// which=2 -> TRANSPOSED fp16 V (g_Vth) via smem staging.
// ---------------------------------------------------------------------------
#define LDB3 48               // bytes per smem row (16 bf16 + pad)
#define ARR3 (128 * LDB3)     // 6144
#define STAGE3 (4 * ARR3)     // 24576
#define PROJ_SMEM (4 * STAGE3)  // 98304
#define VSTR 136              // fp16 stride for Vt staging (pad vs banks)
__global__ __launch_bounds__(256, 2) void proj_mma() {
  extern __shared__ char smc[];
  const uint32_t smem_base = cvta_shared(smc);

  const int which = blockIdx.z;
  const __nv_bfloat16* Xhi = g_Xhi + (size_t)which * Mn * Dn;
  const __nv_bfloat16* Xlo = g_Xlo + (size_t)which * Mn * Dn;
  const __nv_bfloat16* Whi = g_Whi + (size_t)which * Dn * Dn;
  const __nv_bfloat16* Wlo = g_Wlo + (size_t)which * Dn * Dn;

  const int t = threadIdx.x;
  const int lane = t & 31, w = t >> 5;
  const int m0 = blockIdx.y * 128, n0 = blockIdx.x * 128;
  const int m_warp = (w & 1) * 64, n_warp = (w >> 1) * 32;

  const int arr = t >> 6, u = t & 63;
  const __nv_bfloat16* gsrc =
      (arr == 0) ? Xhi : (arr == 1) ? Xlo : (arr == 2) ? Whi : Wlo;
  const int grow0 = (arr < 2) ? m0 : n0;

  auto issue_stage = [&](int kc, int buf) {
    uint32_t sbase = smem_base + buf * STAGE3 + arr * ARR3;
    const int k0 = kc * 16;
#pragma unroll
    for (int j = 0; j < 4; j++) {
      int c = u * 4 + j;
      int row = c >> 1, ch = c & 1;
      cp16(sbase + row * LDB3 + ch * 16,
           gsrc + (size_t)(grow0 + row) * Dn + k0 + ch * 8);
    }
    CP_COMMIT();
  };

  float acc[4][4][4];
#pragma unroll
  for (int i = 0; i < 4; i++)
#pragma unroll
    for (int j = 0; j < 4; j++)
#pragma unroll
      for (int r = 0; r < 4; r++) acc[i][j][r] = 0.f;

  issue_stage(0, 0);
  issue_stage(1, 1);
  issue_stage(2, 2);

  const uint32_t a_off = (lane & 15) * LDB3 + ((lane >> 4) << 4);
  const uint32_t b_off =
      ((lane & 7) + ((lane >> 4) << 3)) * LDB3 + (((lane >> 3) & 1) << 4);

  for (int kc = 0; kc < 64; kc++) {
    if (kc < 62) { CP_WAIT2(); } else if (kc < 63) { CP_WAIT1(); } else {
      CP_WAIT0();
    }
    __syncthreads();
    const uint32_t sA = smem_base + (kc & 3) * STAGE3;
    const uint32_t sAl = sA + ARR3;
    const uint32_t sBh = sA + 2 * ARR3;
    const uint32_t sBl = sA + 3 * ARR3;

    uint32_t ahi[4][4], alo[4][4];
#pragma unroll
    for (int mf = 0; mf < 4; mf++) {
      uint32_t ro = (m_warp + mf * 16) * LDB3 + a_off;
      ldmx4(ahi[mf], sA + ro);
      ldmx4(alo[mf], sAl + ro);
    }
    uint32_t bh[4][2], bl[4][2];
#pragma unroll
    for (int ng = 0; ng < 2; ng++) {
      uint32_t ro = (n_warp + ng * 16) * LDB3 + b_off;
      uint32_t r4[4];
      ldmx4(r4, sBh + ro);
      bh[2 * ng][0] = r4[0]; bh[2 * ng][1] = r4[1];
      bh[2 * ng + 1][0] = r4[2]; bh[2 * ng + 1][1] = r4[3];
      ldmx4(r4, sBl + ro);
      bl[2 * ng][0] = r4[0]; bl[2 * ng][1] = r4[1];
      bl[2 * ng + 1][0] = r4[2]; bl[2 * ng + 1][1] = r4[3];
    }
#pragma unroll
    for (int mf = 0; mf < 4; mf++)
#pragma unroll
      for (int nf = 0; nf < 4; nf++) {
        mma_bf16(acc[mf][nf], ahi[mf], bh[nf]);
        mma_bf16(acc[mf][nf], ahi[mf], bl[nf]);
        mma_bf16(acc[mf][nf], alo[mf], bh[nf]);
      }
    if (kc + 3 < 64) issue_stage(kc + 3, (kc + 3) & 3);
  }

  const int r0 = lane >> 2, cc = (lane & 3) * 2;
  if (which == 2) {
    // ---- stage V^T (fp16) into smem: vt[n_local][m_local], stride VSTR ----
    __half* vt = (__half*)smc;
#pragma unroll
    for (int mf = 0; mf < 4; mf++) {
      int ml = m_warp + mf * 16 + r0;
#pragma unroll
      for (int nf = 0; nf < 4; nf++) {
        int nl = n_warp + nf * 8 + cc;
        vt[(size_t)nl * VSTR + ml] = __float2half_rn(acc[mf][nf][0]);
        vt[(size_t)(nl + 1) * VSTR + ml] = __float2half_rn(acc[mf][nf][1]);
        vt[(size_t)nl * VSTR + ml + 8] = __float2half_rn(acc[mf][nf][2]);
        vt[(size_t)(nl + 1) * VSTR + ml + 8] = __float2half_rn(acc[mf][nf][3]);
      }
    }
    __syncthreads();
    // ---- coalesced write-out: thread t covers half a d-row (64 fp16) ----
    const int nl = t >> 1, half = t & 1;
    const int b = m0 >> 11;          // batch
    const int s0 = (m0 & 2047) + half * 64;
    const int h = (n0 + nl) >> 6, d = (n0 + nl) & 63;
    __half* dst = g_Vth + ((size_t)(b * Hn + h) * 64 + d) * Sn + s0;
    const __half* src = vt + (size_t)nl * VSTR + half * 64;
#pragma unroll
    for (int j = 0; j < 8; j++)
      *(uint4*)((char*)dst + j * 16) = *(const uint4*)((const char*)src + j * 16);
  } else {
    __nv_bfloat16* Dh = (which == 0) ? g_Qhi : g_Khi;
    __nv_bfloat16* Dl = (which == 0) ? g_Qlo : g_Klo;
    const float sc = (which == 0) ? 0.125f : 1.0f;
#pragma unroll
    for (int mf = 0; mf < 4; mf++) {
      int row = m0 + m_warp + mf * 16 + r0;
#pragma unroll
      for (int nf = 0; nf < 4; nf++) {
        int col = n0 + n_warp + nf * 8 + cc;
        uint32_t hi, lo;
        split_pair(acc[mf][nf][0] * sc, acc[mf][nf][1] * sc, hi, lo);
        *(uint32_t*)((char*)Dh + ((size_t)row * Dn + col) * 2) = hi;
        *(uint32_t*)((char*)Dl + ((size_t)row * Dn + col) * 2) = lo;
        split_pair(acc[mf][nf][2] * sc, acc[mf][nf][3] * sc, hi, lo);
        *(uint32_t*)((char*)Dh + ((size_t)(row + 8) * Dn + col) * 2) = hi;
        *(uint32_t*)((char*)Dl + ((size_t)(row + 8) * Dn + col) * 2) = lo;
      }
    }
  }
}

// ---------------------------------------------------------------------------
// Kernel 2: flash attention (R10 version). QK^T via bf16 3-MMA split; PV via
// fp16 single MMA. grid = (32, 16, 4), 128 threads = 4 warps; LPT.
// ---------------------------------------------------------------------------
#define LDF 144
#define FARR (64 * LDF)       // 9216
#define FSTAGE (3 * FARR)     // 27648
#define FLASH_SMEM (2 * FARR + 2 * FSTAGE)  // 73728
__global__ __launch_bounds__(128, 2) void flash_tc() {
  extern __shared__ char smf[];
  const uint32_t sb = cvta_shared(smf);
  const int qb = 31 - blockIdx.x;  // LPT: longest first
  const int h = blockIdx.y, b = blockIdx.z;
  const int bh = b * Hn + h;
  const int t = threadIdx.x, lane = t & 31, w = t >> 5;

  // ---- load Q hi/lo into smem (plain loads) ----
  {
    int r = t >> 1, c32 = (t & 1) * 32;  // row, 32-bf16 half
    size_t src = ((size_t)(b * Sn + qb * 64 + r)) * Dn + h * 64 + c32;
    uint4 q0 = *(const uint4*)((const char*)g_Qhi + src * 2);
    uint4 q1 = *(const uint4*)((const char*)g_Qhi + src * 2 + 16);
    uint4 q2 = *(const uint4*)((const char*)g_Qhi + src * 2 + 32);
    uint4 q3 = *(const uint4*)((const char*)g_Qhi + src * 2 + 48);
    char* dstH = smf + r * LDF + c32 * 2;
    *(uint4*)dstH = q0; *(uint4*)(dstH + 16) = q1;
    *(uint4*)(dstH + 32) = q2; *(uint4*)(dstH + 48) = q3;
    q0 = *(const uint4*)((const char*)g_Qlo + src * 2);
    q1 = *(const uint4*)((const char*)g_Qlo + src * 2 + 16);
    q2 = *(const uint4*)((const char*)g_Qlo + src * 2 + 32);
    q3 = *(const uint4*)((const char*)g_Qlo + src * 2 + 48);
    char* dstL = smf + FARR + r * LDF + c32 * 2;
    *(uint4*)dstL = q0; *(uint4*)(dstL + 16) = q1;
    *(uint4*)(dstL + 32) = q2; *(uint4*)(dstL + 48) = q3;
  }

  // cp.async stage loader: warps 0,1 -> K hi/lo; warps 2,3 -> half of Vt each
  auto issue_kv = [&](int kb2, int buf) {
    uint32_t stage = sb + 2 * FARR + buf * FSTAGE;
    if (w < 2) {
      const __nv_bfloat16* src = (w == 0) ? g_Khi : g_Klo;
      size_t base = ((size_t)(b * Sn + kb2 * 64)) * Dn + h * 64;
      uint32_t sbase = stage + w * FARR;
#pragma unroll
      for (int j = 0; j < 16; j++) {
        int idx = lane + j * 32;
        int row = idx >> 3, ch = idx & 7;
        cp16(sbase + row * LDF + ch * 16, src + base + row * Dn + ch * 8);
      }
    } else {
      uint32_t sbase = stage + 2 * FARR;
      size_t base = (size_t)bh * 64 * Sn + kb2 * 64;
      const int half = w - 2;
#pragma unroll
      for (int j = 0; j < 8; j++) {
        int idx = lane + j * 32 + half * 256;
        int row = idx >> 3, ch = idx & 7;
        cp16(sbase + row * LDF + ch * 16, g_Vth + base + row * Sn + ch * 8);
      }
    }
    CP_COMMIT();
  };

  issue_kv(0, 0);
  if (qb >= 1) issue_kv(1, 1);

  const int r0 = lane >> 2, cq = (lane & 3) * 2;
  const uint32_t a_off = (lane & 15) * LDF + ((lane >> 4) << 4);
  const uint32_t b_off =
      ((lane & 7) + ((lane >> 4) << 3)) * LDF + (((lane >> 3) & 1) << 4);

  // ---- hoist loop-invariant Q fragments to registers ----
  __syncthreads();  // Q smem visible to all warps
  uint32_t qh[4][4], ql[4][4];
#pragma unroll
  for (int ks = 0; ks < 4; ks++) {
    ldmx4(qh[ks], sb + (w * 16) * LDF + ks * 32 + a_off);
    ldmx4(ql[ks], sb + FARR + (w * 16) * LDF + ks * 32 + a_off);
  }

  float m0 = -1e30f, m1 = -1e30f, l0 = 0.f, l1 = 0.f;
  float O[8][4];
#pragma unroll
  for (int i = 0; i < 8; i++)
#pragma unroll
    for (int j = 0; j < 4; j++) O[i][j] = 0.f;

  const int ig0 = qb * 64 + w * 16 + r0, ig1 = ig0 + 8;

  for (int kb = 0; kb <= qb; kb++) {
    if (kb < qb) { CP_WAIT1(); } else { CP_WAIT0(); }
    __syncthreads();
    const uint32_t st = sb + 2 * FARR + (kb & 1) * FSTAGE;
    const uint32_t sKh = st, sKl = st + FARR;
    const uint32_t sVt = st + 2 * FARR;

    // ---- S = Qs @ K^T (3-MMA bf16 split) ----
    float sc[8][4];
#pragma unroll
    for (int i = 0; i < 8; i++)
#pragma unroll
      for (int j = 0; j < 4; j++) sc[i][j] = 0.f;
#pragma unroll
    for (int ks = 0; ks < 4; ks++) {
#pragma unroll
      for (int ng = 0; ng < 4; ng++) {
        uint32_t kh4[4], kl4[4];
        ldmx4(kh4, sKh + (ng * 16) * LDF + ks * 32 + b_off);
        ldmx4(kl4, sKl + (ng * 16) * LDF + ks * 32 + b_off);
        mma_bf16(sc[2 * ng], qh[ks], kh4);
        mma_bf16(sc[2 * ng], qh[ks], kl4);
        mma_bf16(sc[2 * ng], ql[ks], kh4);
        mma_bf16(sc[2 * ng + 1], qh[ks], kh4 + 2);
        mma_bf16(sc[2 * ng + 1], qh[ks], kl4 + 2);
        mma_bf16(sc[2 * ng + 1], ql[ks], kh4 + 2);
      }
    }

    // ---- causal mask on diag tile ----
    if (kb == qb) {
#pragma unroll
      for (int nf = 0; nf < 8; nf++) {
        int jg = kb * 64 + nf * 8 + cq;
        if (jg > ig0) sc[nf][0] = -1e30f;
        if (jg + 1 > ig0) sc[nf][1] = -1e30f;
        if (jg > ig1) sc[nf][2] = -1e30f;
        if (jg + 1 > ig1) sc[nf][3] = -1e30f;
      }
    }

    // ---- online softmax (registers only) ----
    float mx0 = -1e30f, mx1 = -1e30f;
#pragma unroll
    for (int nf = 0; nf < 8; nf++) {
      mx0 = fmaxf(mx0, fmaxf(sc[nf][0], sc[nf][1]));
      mx1 = fmaxf(mx1, fmaxf(sc[nf][2], sc[nf][3]));
    }
    mx0 = fmaxf(mx0, __shfl_xor_sync(0xffffffffu, mx0, 1));
    mx0 = fmaxf(mx0, __shfl_xor_sync(0xffffffffu, mx0, 2));
    mx1 = fmaxf(mx1, __shfl_xor_sync(0xffffffffu, mx1, 1));
    mx1 = fmaxf(mx1, __shfl_xor_sync(0xffffffffu, mx1, 2));
    float mn0 = fmaxf(m0, mx0), mn1 = fmaxf(m1, mx1);
    float al0 = __expf(m0 - mn0), al1 = __expf(m1 - mn1);

    const size_t tri = (size_t)bh * NTRI + (size_t)(qb * (qb + 1) / 2) + kb;
    if ((lane & 3) == 0) {
      g_mr[tri * 64 + w * 16 + r0] = mn0;
      g_mr[tri * 64 + w * 16 + r0 + 8] = mn1;
    }
    __half* Pt = g_P + tri * 4096;

    float rs0 = 0.f, rs1 = 0.f;
    uint32_t pa[4][4];  // fp16 A-fragments for PV (same bits as stored P)
#pragma unroll
    for (int nf = 0; nf < 8; nf++) {
      float p0 = __expf(sc[nf][0] - mn0);
      float p1 = __expf(sc[nf][1] - mn0);
      float p2 = __expf(sc[nf][2] - mn1);
      float p3 = __expf(sc[nf][3] - mn1);
      rs0 += p0 + p1;
      rs1 += p2 + p3;
      __half2 h01 = __float22half2_rn(make_float2(p0, p1));
      __half2 h23 = __float22half2_rn(make_float2(p2, p3));
      int colb = nf * 8 + cq;
      __stcs((__half2*)(Pt + (w * 16 + r0) * 64 + colb), h01);
      __stcs((__half2*)(Pt + (w * 16 + r0 + 8) * 64 + colb), h23);
      uint32_t u01, u23;
      memcpy(&u01, &h01, 4);
      memcpy(&u23, &h23, 4);
      int kc = nf >> 1, half = nf & 1;
      pa[kc][half * 2 + 0] = u01;
      pa[kc][half * 2 + 1] = u23;
    }
    rs0 += __shfl_xor_sync(0xffffffffu, rs0, 1);
    rs0 += __shfl_xor_sync(0xffffffffu, rs0, 2);
    rs1 += __shfl_xor_sync(0xffffffffu, rs1, 1);
    rs1 += __shfl_xor_sync(0xffffffffu, rs1, 2);
    l0 = l0 * al0 + rs0;
    l1 = l1 * al1 + rs1;
    m0 = mn0;
    m1 = mn1;
#pragma unroll
    for (int nf = 0; nf < 8; nf++) {
      O[nf][0] *= al0; O[nf][1] *= al0;
      O[nf][2] *= al1; O[nf][3] *= al1;
    }

    // ---- O += P @ V (single fp16 MMA; B = Vt fp16) ----
#pragma unroll
    for (int kc = 0; kc < 4; kc++) {
#pragma unroll
      for (int ng = 0; ng < 4; ng++) {
        uint32_t v4[4];
        ldmx4(v4, sVt + (ng * 16) * LDF + kc * 32 + b_off);
        mma_fp16(O[2 * ng], pa[kc], v4);
        mma_fp16(O[2 * ng + 1], pa[kc], v4 + 2);
      }
    }
    __syncthreads();
    if (kb + 2 <= qb) issue_kv(kb + 2, kb & 1);
  }

  // ---- epilogue ----
  const float i0 = 1.0f / l0, i1 = 1.0f / l1;
  float* Cg = g_ctx + ((size_t)(b * Sn + qb * 64)) * Dn + h * 64;
#pragma unroll
  for (int nf = 0; nf < 8; nf++) {
    int colb = nf * 8 + cq;
    *(float2*)(Cg + (size_t)(w * 16 + r0) * Dn + colb) =
        make_float2(O[nf][0] * i0, O[nf][1] * i0);
    *(float2*)(Cg + (size_t)(w * 16 + r0 + 8) * Dn + colb) =
        make_float2(O[nf][2] * i1, O[nf][3] * i1);
  }
  if ((lane & 3) == 0) {
    int base = bh * Sn + qb * 64 + w * 16 + r0;
    g_m[base] = m0; g_l[base] = l0;
    g_m[base + 8] = m1; g_l[base + 8] = l1;
  }
}

// ---------------------------------------------------------------------------
// Kernel 3: attn materialization, 4-tile unrolled version.
// grid = (8 kb-groups, 32 qb, 64 bh), 256 threads. Each block handles 4
// consecutive kb tiles with fully-unrolled independent bodies (4x MLP vs
// one-tile blocks, 16384 blocks for parallelism). m/l loaded once.
// ---------------------------------------------------------------------------
__global__ __launch_bounds__(256) void attn_write_fast(
    float* __restrict__ attn) {
  const int kg = blockIdx.x, qb = blockIdx.y, bh = blockIdx.z;
  const int t = threadIdx.x;
  const int row = t >> 2, c16 = (t & 3) << 4;
  const int rbase = bh * Sn + qb * 64 + row;
  const float mf = g_m[rbase];
  const float inv = 1.0f / g_l[rbase];
  const size_t tri0 = (size_t)bh * NTRI + (size_t)(qb * (qb + 1) / 2);
  float* dst0 = attn + ((size_t)bh * Sn + qb * 64 + row) * Sn + c16;

#pragma unroll
  for (int u = 0; u < 4; u++) {
    const int kb = kg * 4 + u;
    float* dst = dst0 + kb * 64;
    if (kb > qb) {
      const float4 z = make_float4(0.f, 0.f, 0.f, 0.f);
#pragma unroll
      for (int j = 0; j < 4; j++) __stcs((float4*)(dst + 4 * j), z);
    } else {
      const float scale =
          __expf(g_mr[(tri0 + kb) * 64 + row] - mf) * inv;
      const __half2* Pt =
          (const __half2*)(g_P + (tri0 + kb) * 4096 + row * 64 + c16);
#pragma unroll
      for (int j = 0; j < 4; j++) {
        float2 p0 = __half22float2(__ldcs(Pt + 2 * j));
        float2 p1 = __half22float2(__ldcs(Pt + 2 * j + 1));
        __stcs((float4*)(dst + 4 * j),
               make_float4(p0.x * scale, p0.y * scale, p1.x * scale,
                           p1.y * scale));
      }
    }
  }
}

// ---------------------------------------------------------------------------
// Kernel 4: residual add + LayerNorm.  grid = 8192 rows, 256 threads.
// ---------------------------------------------------------------------------
__global__ __launch_bounds__(256) void ln_kernel(
    const float* __restrict__ res, const float* __restrict__ gamma,
    const float* __restrict__ beta, float* __restrict__ out) {
  const int row = blockIdx.x;
  const int t = threadIdx.x;
  const float4 cv = ((const float4*)(g_ctx + (size_t)row * Dn))[t];
  const float4 rv = ((const float4*)(res + (size_t)row * Dn))[t];
  float x0 = cv.x + rv.x, x1 = cv.y + rv.y, x2 = cv.z + rv.z, x3 = cv.w + rv.w;

  float sum = x0 + x1 + x2 + x3;
  float sq = x0 * x0 + x1 * x1 + x2 * x2 + x3 * x3;
#pragma unroll
  for (int off = 16; off > 0; off >>= 1) {
    sum += __shfl_xor_sync(0xffffffffu, sum, off);
    sq += __shfl_xor_sync(0xffffffffu, sq, off);
  }
  __shared__ float ssum[8], ssq[8];
  const int w = t >> 5, lane = t & 31;
  if (lane == 0) { ssum[w] = sum; ssq[w] = sq; }
  __syncthreads();
  if (w == 0) {
    float a = (lane < 8) ? ssum[lane] : 0.f;
    float b2 = (lane < 8) ? ssq[lane] : 0.f;
#pragma unroll
    for (int off = 4; off > 0; off >>= 1) {
      a += __shfl_xor_sync(0xffffffffu, a, off);
      b2 += __shfl_xor_sync(0xffffffffu, b2, off);
    }
    if (lane == 0) { ssum[0] = a; ssq[0] = b2; }
  }
  __syncthreads();
  const float mean = ssum[0] * (1.0f / 1024.0f);
  const float var = ssq[0] * (1.0f / 1024.0f) - mean * mean;
  const float rstd = rsqrtf(var + 1e-5f);

  const float4 g = ((const float4*)gamma)[t];
  const float4 be = ((const float4*)beta)[t];
  float4 o = make_float4((x0 - mean) * rstd * g.x + be.x,
                         (x1 - mean) * rstd * g.y + be.y,
                         (x2 - mean) * rstd * g.z + be.z,
                         (x3 - mean) * rstd * g.w + be.w);
  ((float4*)(out + (size_t)row * Dn))[t] = o;
}

// ---------------------------------------------------------------------------
// Inputs (metadata order): q, k, v, mask, Wq, Wk, Wv, ln_gamma, ln_beta
// Output: concat(out[B,S,D], attn[B,H,S,S]) as float32.
// ---------------------------------------------------------------------------
extern "C" void kernel_launch(void* const* d_in, const int* in_sizes, int n_in,
                              void* d_out, int out_size) {
  const float* q = (const float*)d_in[0];
  const float* k = (const float*)d_in[1];
  const float* v = (const float*)d_in[2];
  // d_in[3] = mask (int32) — causal tril, applied analytically
  const float* Wq = (const float*)d_in[4];
  const float* Wk = (const float*)d_in[5];
  const float* Wv = (const float*)d_in[6];
  const float* gamma = (const float*)d_in[7];
  const float* beta = (const float*)d_in[8];
  float* out = (float*)d_out;

  cudaFuncSetAttribute(proj_mma, cudaFuncAttributeMaxDynamicSharedMemorySize,
                       PROJ_SMEM);
  cudaFuncSetAttribute(flash_tc, cudaFuncAttributeMaxDynamicSharedMemorySize,
                       FLASH_SMEM);

  prep_inputs<<<dim3(5120, 3), 256>>>(q, k, v, Wq, Wk, Wv);
  proj_mma<<<dim3(8, 64, 3), 256, PROJ_SMEM>>>();
  flash_tc<<<dim3(32, 16, 4), 128, FLASH_SMEM>>>();
  if ((size_t)out_size >= OUT_ELEMS + ATTN_ELEMS) {
    attn_write_fast<<<dim3(8, 32, 64), 256>>>(out + OUT_ELEMS);
  }
  ln_kernel<<<Mn, 256>>>(q, gamma, beta, out);
}

// round 16
// speedup vs baseline: 1.1555x; 1.1176x over previous
#include <cuda_runtime.h>
#include <cuda_bf16.h>
#include <cuda_fp16.h>
#include <math.h>
#include <stdint.h>
#include <string.h>

// Problem constants
#define Bn 4
#define Sn 2048
#define Dn 1024
#define Hn 16
#define Mn (Bn * Sn)                            // 8192 rows
#define OUT_ELEMS ((size_t)Mn * Dn)             // 8,388,608
#define ATTN_ELEMS ((size_t)Bn * Hn * Sn * Sn)  // 268,435,456
#define NTRI 528                                // 32*33/2 lower-tri blocks

// Scratch (device globals; no allocations allowed)
__device__ float g_ctx[(size_t)Mn * Dn];
// fp16 probabilities exp(s - m_run) for lower-tri blocks + per-tile FINAL
// rescale factor exp(m_run - m_final)/l (computed in flash epilogue)
__device__ __align__(16) __half g_P[(size_t)Bn * Hn * NTRI * 4096];
__device__ float g_mr[(size_t)Bn * Hn * NTRI * 64];

// bf16 split inputs for tensor-core projection
__device__ __align__(16) __nv_bfloat16 g_Xhi[(size_t)3 * Mn * Dn];
__device__ __align__(16) __nv_bfloat16 g_Xlo[(size_t)3 * Mn * Dn];
__device__ __align__(16) __nv_bfloat16 g_Whi[(size_t)3 * Dn * Dn];  // [n][k]
__device__ __align__(16) __nv_bfloat16 g_Wlo[(size_t)3 * Dn * Dn];

// bf16 split tensors for flash attention (Q, K) + fp16 transposed V
__device__ __align__(16) __nv_bfloat16 g_Qhi[(size_t)Mn * Dn];  // scaled
__device__ __align__(16) __nv_bfloat16 g_Qlo[(size_t)Mn * Dn];
__device__ __align__(16) __nv_bfloat16 g_Khi[(size_t)Mn * Dn];
__device__ __align__(16) __nv_bfloat16 g_Klo[(size_t)Mn * Dn];
__device__ __align__(16) __half g_Vth[(size_t)Bn * Hn * 64 * Sn];

typedef unsigned long long u64t;

// ---------------------------------------------------------------------------
// helpers
// ---------------------------------------------------------------------------
__device__ __forceinline__ uint32_t cvta_shared(const void* p) {
  uint32_t a;
  asm("{ .reg .u64 t; cvta.to.shared.u64 t, %1; cvt.u32.u64 %0, t; }"
      : "=r"(a) : "l"(p));
  return a;
}
__device__ __forceinline__ void bsplit(float x, unsigned short& hi,
                                       unsigned short& lo) {
  __nv_bfloat16 h = __float2bfloat16_rn(x);
  __nv_bfloat16 l = __float2bfloat16_rn(x - __bfloat162float(h));
  hi = __bfloat16_as_ushort(h);
  lo = __bfloat16_as_ushort(l);
}
// pack pair (x -> low16, y -> high16) as bf16 hi-part and residual lo-part
__device__ __forceinline__ void split_pair(float x, float y, uint32_t& hi,
                                           uint32_t& lo) {
  __nv_bfloat16 xh = __float2bfloat16_rn(x), yh = __float2bfloat16_rn(y);
  float xr = x - __bfloat162float(xh), yr = y - __bfloat162float(yh);
  __nv_bfloat16 xl = __float2bfloat16_rn(xr), yl = __float2bfloat16_rn(yr);
  hi = (uint32_t)__bfloat16_as_ushort(xh) |
       ((uint32_t)__bfloat16_as_ushort(yh) << 16);
  lo = (uint32_t)__bfloat16_as_ushort(xl) |
       ((uint32_t)__bfloat16_as_ushort(yl) << 16);
}

__device__ __forceinline__ void ldmx4(uint32_t* r, uint32_t addr) {
  asm volatile(
      "ldmatrix.sync.aligned.m8n8.x4.shared.b16 {%0,%1,%2,%3}, [%4];"
      : "=r"(r[0]), "=r"(r[1]), "=r"(r[2]), "=r"(r[3])
      : "r"(addr));
}
__device__ __forceinline__ void mma_bf16(float* c, const uint32_t* a,
                                         const uint32_t* b) {
  asm volatile(
      "mma.sync.aligned.m16n8k16.row.col.f32.bf16.bf16.f32 "
      "{%0,%1,%2,%3}, {%4,%5,%6,%7}, {%8,%9}, {%0,%1,%2,%3};"
      : "+f"(c[0]), "+f"(c[1]), "+f"(c[2]), "+f"(c[3])
      : "r"(a[0]), "r"(a[1]), "r"(a[2]), "r"(a[3]), "r"(b[0]), "r"(b[1]));
}
__device__ __forceinline__ void mma_fp16(float* c, const uint32_t* a,
                                         const uint32_t* b) {
  asm volatile(
      "mma.sync.aligned.m16n8k16.row.col.f32.f16.f16.f32 "
      "{%0,%1,%2,%3}, {%4,%5,%6,%7}, {%8,%9}, {%0,%1,%2,%3};"
      : "+f"(c[0]), "+f"(c[1]), "+f"(c[2]), "+f"(c[3])
      : "r"(a[0]), "r"(a[1]), "r"(a[2]), "r"(a[3]), "r"(b[0]), "r"(b[1]));
}
__device__ __forceinline__ void cp16(uint32_t saddr, const void* gaddr) {
  asm volatile("cp.async.cg.shared.global [%0], [%1], 16;" ::"r"(saddr),
               "l"(gaddr));
}
#define CP_COMMIT() asm volatile("cp.async.commit_group;" ::: "memory")
#define CP_WAIT2() asm volatile("cp.async.wait_group 2;" ::: "memory")
#define CP_WAIT1() asm volatile("cp.async.wait_group 1;" ::: "memory")
#define CP_WAIT0() asm volatile("cp.async.wait_group 0;" ::: "memory")

// ---------------------------------------------------------------------------
// Kernel 0: fused input prep. grid (5120, 3), 256 threads.
//   x < 4096: split q/k/v into bf16 hi/lo.
//   x >= 4096: transpose + split W (32x32 tile per block).
// ---------------------------------------------------------------------------
__global__ __launch_bounds__(256) void prep_inputs(
    const float* __restrict__ q, const float* __restrict__ k,
    const float* __restrict__ v, const float* __restrict__ Wq,
    const float* __restrict__ Wk, const float* __restrict__ Wv) {
  const int which = blockIdx.y;
  const int t = threadIdx.x;
  __shared__ float tile[32][33];

  if (blockIdx.x < 4096) {
    const float* X = (which == 0) ? q : (which == 1) ? k : v;
    size_t off = ((size_t)blockIdx.x * 256 + t) * 8;
    float4 a = *(const float4*)(X + off);
    float4 b = *(const float4*)(X + off + 4);
    unsigned short h[8], l[8];
    bsplit(a.x, h[0], l[0]); bsplit(a.y, h[1], l[1]);
    bsplit(a.z, h[2], l[2]); bsplit(a.w, h[3], l[3]);
    bsplit(b.x, h[4], l[4]); bsplit(b.y, h[5], l[5]);
    bsplit(b.z, h[6], l[6]); bsplit(b.w, h[7], l[7]);
    uint4 uh, ul;
    uh.x = (uint32_t)h[0] | ((uint32_t)h[1] << 16);
    uh.y = (uint32_t)h[2] | ((uint32_t)h[3] << 16);
    uh.z = (uint32_t)h[4] | ((uint32_t)h[5] << 16);
    uh.w = (uint32_t)h[6] | ((uint32_t)h[7] << 16);
    ul.x = (uint32_t)l[0] | ((uint32_t)l[1] << 16);
    ul.y = (uint32_t)l[2] | ((uint32_t)l[3] << 16);
    ul.z = (uint32_t)l[4] | ((uint32_t)l[5] << 16);
    ul.w = (uint32_t)l[6] | ((uint32_t)l[7] << 16);
    size_t dst = (size_t)which * Mn * Dn + off;
    *(uint4*)((char*)g_Xhi + dst * 2) = uh;
    *(uint4*)((char*)g_Xlo + dst * 2) = ul;
  } else {
    const float* W = (which == 0) ? Wq : (which == 1) ? Wk : Wv;
    const int bx = blockIdx.x - 4096;
    const int x0 = (bx & 31) * 32, y0 = (bx >> 5) * 32;
    const int tx = t & 31, ty = t >> 5;  // 32 x 8
#pragma unroll
    for (int j = 0; j < 32; j += 8)
      tile[ty + j][tx] = W[(size_t)(y0 + ty + j) * Dn + x0 + tx];
    __syncthreads();
    size_t base = (size_t)which * Dn * Dn;
#pragma unroll
    for (int j = 0; j < 32; j += 8) {
      float x = tile[tx][ty + j];
      unsigned short h, l;
      bsplit(x, h, l);
      size_t dst = base + (size_t)(x0 + ty + j) * Dn + y0 + tx;
      ((unsigned short*)g_Whi)[dst] = h;
      ((unsigned short*)g_Wlo)[dst] = l;
    }
  }
}

// ---------------------------------------------------------------------------
// Kernel 1: QKV projection via mma.sync bf16 (4-stage pipeline).
// Epilogue fused: which=0 -> Qhi/Qlo (scaled 0.125), which=1 -> Khi/Klo,
// which=2 -> TRANSPOSED fp16 V (g_Vth) via smem staging.
// ---------------------------------------------------------------------------
#define LDB3 48               // bytes per smem row (16 bf16 + pad)
#define ARR3 (128 * LDB3)     // 6144
#define STAGE3 (4 * ARR3)     // 24576
#define PROJ_SMEM (4 * STAGE3)  // 98304
#define VSTR 136              // fp16 stride for Vt staging (pad vs banks)
__global__ __launch_bounds__(256, 2) void proj_mma() {
  extern __shared__ char smc[];
  const uint32_t smem_base = cvta_shared(smc);

  const int which = blockIdx.z;
  const __nv_bfloat16* Xhi = g_Xhi + (size_t)which * Mn * Dn;
  const __nv_bfloat16* Xlo = g_Xlo + (size_t)which * Mn * Dn;
  const __nv_bfloat16* Whi = g_Whi + (size_t)which * Dn * Dn;
  const __nv_bfloat16* Wlo = g_Wlo + (size_t)which * Dn * Dn;

  const int t = threadIdx.x;
  const int lane = t & 31, w = t >> 5;
  const int m0 = blockIdx.y * 128, n0 = blockIdx.x * 128;
  const int m_warp = (w & 1) * 64, n_warp = (w >> 1) * 32;

  const int arr = t >> 6, u = t & 63;
  const __nv_bfloat16* gsrc =
      (arr == 0) ? Xhi : (arr == 1) ? Xlo : (arr == 2) ? Whi : Wlo;
  const int grow0 = (arr < 2) ? m0 : n0;

  auto issue_stage = [&](int kc, int buf) {
    uint32_t sbase = smem_base + buf * STAGE3 + arr * ARR3;
    const int k0 = kc * 16;
#pragma unroll
    for (int j = 0; j < 4; j++) {
      int c = u * 4 + j;
      int row = c >> 1, ch = c & 1;
      cp16(sbase + row * LDB3 + ch * 16,
           gsrc + (size_t)(grow0 + row) * Dn + k0 + ch * 8);
    }
    CP_COMMIT();
  };

  float acc[4][4][4];
#pragma unroll
  for (int i = 0; i < 4; i++)
#pragma unroll
    for (int j = 0; j < 4; j++)
#pragma unroll
      for (int r = 0; r < 4; r++) acc[i][j][r] = 0.f;

  issue_stage(0, 0);
  issue_stage(1, 1);
  issue_stage(2, 2);

  const uint32_t a_off = (lane & 15) * LDB3 + ((lane >> 4) << 4);
  const uint32_t b_off =
      ((lane & 7) + ((lane >> 4) << 3)) * LDB3 + (((lane >> 3) & 1) << 4);

  for (int kc = 0; kc < 64; kc++) {
    if (kc < 62) { CP_WAIT2(); } else if (kc < 63) { CP_WAIT1(); } else {
      CP_WAIT0();
    }
    __syncthreads();
    const uint32_t sA = smem_base + (kc & 3) * STAGE3;
    const uint32_t sAl = sA + ARR3;
    const uint32_t sBh = sA + 2 * ARR3;
    const uint32_t sBl = sA + 3 * ARR3;

    uint32_t ahi[4][4], alo[4][4];
#pragma unroll
    for (int mf = 0; mf < 4; mf++) {
      uint32_t ro = (m_warp + mf * 16) * LDB3 + a_off;
      ldmx4(ahi[mf], sA + ro);
      ldmx4(alo[mf], sAl + ro);
    }
    uint32_t bh[4][2], bl[4][2];
#pragma unroll
    for (int ng = 0; ng < 2; ng++) {
      uint32_t ro = (n_warp + ng * 16) * LDB3 + b_off;
      uint32_t r4[4];
      ldmx4(r4, sBh + ro);
      bh[2 * ng][0] = r4[0]; bh[2 * ng][1] = r4[1];
      bh[2 * ng + 1][0] = r4[2]; bh[2 * ng + 1][1] = r4[3];
      ldmx4(r4, sBl + ro);
      bl[2 * ng][0] = r4[0]; bl[2 * ng][1] = r4[1];
      bl[2 * ng + 1][0] = r4[2]; bl[2 * ng + 1][1] = r4[3];
    }
#pragma unroll
    for (int mf = 0; mf < 4; mf++)
#pragma unroll
      for (int nf = 0; nf < 4; nf++) {
        mma_bf16(acc[mf][nf], ahi[mf], bh[nf]);
        mma_bf16(acc[mf][nf], ahi[mf], bl[nf]);
        mma_bf16(acc[mf][nf], alo[mf], bh[nf]);
      }
    if (kc + 3 < 64) issue_stage(kc + 3, (kc + 3) & 3);
  }

  const int r0 = lane >> 2, cc = (lane & 3) * 2;
  if (which == 2) {
    // ---- stage V^T (fp16) into smem: vt[n_local][m_local], stride VSTR ----
    __half* vt = (__half*)smc;
#pragma unroll
    for (int mf = 0; mf < 4; mf++) {
      int ml = m_warp + mf * 16 + r0;
#pragma unroll
      for (int nf = 0; nf < 4; nf++) {
        int nl = n_warp + nf * 8 + cc;
        vt[(size_t)nl * VSTR + ml] = __float2half_rn(acc[mf][nf][0]);
        vt[(size_t)(nl + 1) * VSTR + ml] = __float2half_rn(acc[mf][nf][1]);
        vt[(size_t)nl * VSTR + ml + 8] = __float2half_rn(acc[mf][nf][2]);
        vt[(size_t)(nl + 1) * VSTR + ml + 8] = __float2half_rn(acc[mf][nf][3]);
      }
    }
    __syncthreads();
    // ---- coalesced write-out: thread t covers half a d-row (64 fp16) ----
    const int nl = t >> 1, half = t & 1;
    const int b = m0 >> 11;          // batch
    const int s0 = (m0 & 2047) + half * 64;
    const int h = (n0 + nl) >> 6, d = (n0 + nl) & 63;
    __half* dst = g_Vth + ((size_t)(b * Hn + h) * 64 + d) * Sn + s0;
    const __half* src = vt + (size_t)nl * VSTR + half * 64;
#pragma unroll
    for (int j = 0; j < 8; j++)
      *(uint4*)((char*)dst + j * 16) = *(const uint4*)((const char*)src + j * 16);
  } else {
    __nv_bfloat16* Dh = (which == 0) ? g_Qhi : g_Khi;
    __nv_bfloat16* Dl = (which == 0) ? g_Qlo : g_Klo;
    const float sc = (which == 0) ? 0.125f : 1.0f;
#pragma unroll
    for (int mf = 0; mf < 4; mf++) {
      int row = m0 + m_warp + mf * 16 + r0;
#pragma unroll
      for (int nf = 0; nf < 4; nf++) {
        int col = n0 + n_warp + nf * 8 + cc;
        uint32_t hi, lo;
        split_pair(acc[mf][nf][0] * sc, acc[mf][nf][1] * sc, hi, lo);
        *(uint32_t*)((char*)Dh + ((size_t)row * Dn + col) * 2) = hi;
        *(uint32_t*)((char*)Dl + ((size_t)row * Dn + col) * 2) = lo;
        split_pair(acc[mf][nf][2] * sc, acc[mf][nf][3] * sc, hi, lo);
        *(uint32_t*)((char*)Dh + ((size_t)(row + 8) * Dn + col) * 2) = hi;
        *(uint32_t*)((char*)Dl + ((size_t)(row + 8) * Dn + col) * 2) = lo;
      }
    }
  }
}

// ---------------------------------------------------------------------------
// Kernel 2: flash attention. QK^T via bf16 3-MMA split; PV via fp16 single
// MMA. grid = (32, 16, 4), 128 threads = 4 warps; LPT.
// Per-tile running maxes kept in smem (Q-region overlay, R12-validated);
// epilogue writes FINAL rescale factors exp(m_run-m_final)/l into g_mr so
// attn_write needs a single scalar load per tile.
// ---------------------------------------------------------------------------
#define LDF 144
#define FARR (64 * LDF)       // 9216
#define FSTAGE (3 * FARR)     // 27648
#define FLASH_SMEM (2 * FARR + 2 * FSTAGE)  // 73728
__global__ __launch_bounds__(128, 2) void flash_tc() {
  extern __shared__ char smf[];
  const uint32_t sb = cvta_shared(smf);
  float* smr = (float*)smf;  // [32][64] running max; overlays Q region
  const int qb = 31 - blockIdx.x;  // LPT: longest first
  const int h = blockIdx.y, b = blockIdx.z;
  const int bh = b * Hn + h;
  const int t = threadIdx.x, lane = t & 31, w = t >> 5;

  // ---- load Q hi/lo into smem (plain loads) ----
  {
    int r = t >> 1, c32 = (t & 1) * 32;  // row, 32-bf16 half
    size_t src = ((size_t)(b * Sn + qb * 64 + r)) * Dn + h * 64 + c32;
    uint4 q0 = *(const uint4*)((const char*)g_Qhi + src * 2);
    uint4 q1 = *(const uint4*)((const char*)g_Qhi + src * 2 + 16);
    uint4 q2 = *(const uint4*)((const char*)g_Qhi + src * 2 + 32);
    uint4 q3 = *(const uint4*)((const char*)g_Qhi + src * 2 + 48);
    char* dstH = smf + r * LDF + c32 * 2;
    *(uint4*)dstH = q0; *(uint4*)(dstH + 16) = q1;
    *(uint4*)(dstH + 32) = q2; *(uint4*)(dstH + 48) = q3;
    q0 = *(const uint4*)((const char*)g_Qlo + src * 2);
    q1 = *(const uint4*)((const char*)g_Qlo + src * 2 + 16);
    q2 = *(const uint4*)((const char*)g_Qlo + src * 2 + 32);
    q3 = *(const uint4*)((const char*)g_Qlo + src * 2 + 48);
    char* dstL = smf + FARR + r * LDF + c32 * 2;
    *(uint4*)dstL = q0; *(uint4*)(dstL + 16) = q1;
    *(uint4*)(dstL + 32) = q2; *(uint4*)(dstL + 48) = q3;
  }

  // cp.async stage loader: warps 0,1 -> K hi/lo; warps 2,3 -> half of Vt each
  auto issue_kv = [&](int kb2, int buf) {
    uint32_t stage = sb + 2 * FARR + buf * FSTAGE;
    if (w < 2) {
      const __nv_bfloat16* src = (w == 0) ? g_Khi : g_Klo;
      size_t base = ((size_t)(b * Sn + kb2 * 64)) * Dn + h * 64;
      uint32_t sbase = stage + w * FARR;
#pragma unroll
      for (int j = 0; j < 16; j++) {
        int idx = lane + j * 32;
        int row = idx >> 3, ch = idx & 7;
        cp16(sbase + row * LDF + ch * 16, src + base + row * Dn + ch * 8);
      }
    } else {
      uint32_t sbase = stage + 2 * FARR;
      size_t base = (size_t)bh * 64 * Sn + kb2 * 64;
      const int half = w - 2;
#pragma unroll
      for (int j = 0; j < 8; j++) {
        int idx = lane + j * 32 + half * 256;
        int row = idx >> 3, ch = idx & 7;
        cp16(sbase + row * LDF + ch * 16, g_Vth + base + row * Sn + ch * 8);
      }
    }
    CP_COMMIT();
  };

  issue_kv(0, 0);
  if (qb >= 1) issue_kv(1, 1);

  const int r0 = lane >> 2, cq = (lane & 3) * 2;
  const uint32_t a_off = (lane & 15) * LDF + ((lane >> 4) << 4);
  const uint32_t b_off =
      ((lane & 7) + ((lane >> 4) << 3)) * LDF + (((lane >> 3) & 1) << 4);

  // ---- hoist loop-invariant Q fragments to registers ----
  __syncthreads();  // Q smem visible to all warps
  uint32_t qh[4][4], ql[4][4];
#pragma unroll
  for (int ks = 0; ks < 4; ks++) {
    ldmx4(qh[ks], sb + (w * 16) * LDF + ks * 32 + a_off);
    ldmx4(ql[ks], sb + FARR + (w * 16) * LDF + ks * 32 + a_off);
  }
  // Q smem region is dead after this; smr overlays it. The __syncthreads at
  // the top of the kb loop orders the hoist against smr writes.

  float m0 = -1e30f, m1 = -1e30f, l0 = 0.f, l1 = 0.f;
  float O[8][4];
#pragma unroll
  for (int i = 0; i < 8; i++)
#pragma unroll
    for (int j = 0; j < 4; j++) O[i][j] = 0.f;

  const int ig0 = qb * 64 + w * 16 + r0, ig1 = ig0 + 8;

  for (int kb = 0; kb <= qb; kb++) {
    if (kb < qb) { CP_WAIT1(); } else { CP_WAIT0(); }
    __syncthreads();
    const uint32_t st = sb + 2 * FARR + (kb & 1) * FSTAGE;
    const uint32_t sKh = st, sKl = st + FARR;
    const uint32_t sVt = st + 2 * FARR;

    // ---- S = Qs @ K^T (3-MMA bf16 split) ----
    float sc[8][4];
#pragma unroll
    for (int i = 0; i < 8; i++)
#pragma unroll
      for (int j = 0; j < 4; j++) sc[i][j] = 0.f;
#pragma unroll
    for (int ks = 0; ks < 4; ks++) {
#pragma unroll
      for (int ng = 0; ng < 4; ng++) {
        uint32_t kh4[4], kl4[4];
        ldmx4(kh4, sKh + (ng * 16) * LDF + ks * 32 + b_off);
        ldmx4(kl4, sKl + (ng * 16) * LDF + ks * 32 + b_off);
        mma_bf16(sc[2 * ng], qh[ks], kh4);
        mma_bf16(sc[2 * ng], qh[ks], kl4);
        mma_bf16(sc[2 * ng], ql[ks], kh4);
        mma_bf16(sc[2 * ng + 1], qh[ks], kh4 + 2);
        mma_bf16(sc[2 * ng + 1], qh[ks], kl4 + 2);
        mma_bf16(sc[2 * ng + 1], ql[ks], kh4 + 2);
      }
    }

    // ---- causal mask on diag tile ----
    if (kb == qb) {
#pragma unroll
      for (int nf = 0; nf < 8; nf++) {
        int jg = kb * 64 + nf * 8 + cq;
        if (jg > ig0) sc[nf][0] = -1e30f;
        if (jg + 1 > ig0) sc[nf][1] = -1e30f;
        if (jg > ig1) sc[nf][2] = -1e30f;
        if (jg + 1 > ig1) sc[nf][3] = -1e30f;
      }
    }

    // ---- online softmax (registers only) ----
    float mx0 = -1e30f, mx1 = -1e30f;
#pragma unroll
    for (int nf = 0; nf < 8; nf++) {
      mx0 = fmaxf(mx0, fmaxf(sc[nf][0], sc[nf][1]));
      mx1 = fmaxf(mx1, fmaxf(sc[nf][2], sc[nf][3]));
    }
    mx0 = fmaxf(mx0, __shfl_xor_sync(0xffffffffu, mx0, 1));
    mx0 = fmaxf(mx0, __shfl_xor_sync(0xffffffffu, mx0, 2));
    mx1 = fmaxf(mx1, __shfl_xor_sync(0xffffffffu, mx1, 1));
    mx1 = fmaxf(mx1, __shfl_xor_sync(0xffffffffu, mx1, 2));
    float mn0 = fmaxf(m0, mx0), mn1 = fmaxf(m1, mx1);
    float al0 = __expf(m0 - mn0), al1 = __expf(m1 - mn1);

    // per-tile running max -> smem (used in epilogue for final scales)
    if ((lane & 3) == 0) {
      smr[kb * 64 + w * 16 + r0] = mn0;
      smr[kb * 64 + w * 16 + r0 + 8] = mn1;
    }
    const size_t tri = (size_t)bh * NTRI + (size_t)(qb * (qb + 1) / 2) + kb;
    __half* Pt = g_P + tri * 4096;

    float rs0 = 0.f, rs1 = 0.f;
    uint32_t pa[4][4];  // fp16 A-fragments for PV (same bits as stored P)
#pragma unroll
    for (int nf = 0; nf < 8; nf++) {
      float p0 = __expf(sc[nf][0] - mn0);
      float p1 = __expf(sc[nf][1] - mn0);
      float p2 = __expf(sc[nf][2] - mn1);
      float p3 = __expf(sc[nf][3] - mn1);
      rs0 += p0 + p1;
      rs1 += p2 + p3;
      __half2 h01 = __float22half2_rn(make_float2(p0, p1));
      __half2 h23 = __float22half2_rn(make_float2(p2, p3));
      int colb = nf * 8 + cq;
      __stcs((__half2*)(Pt + (w * 16 + r0) * 64 + colb), h01);
      __stcs((__half2*)(Pt + (w * 16 + r0 + 8) * 64 + colb), h23);
      uint32_t u01, u23;
      memcpy(&u01, &h01, 4);
      memcpy(&u23, &h23, 4);
      int kc = nf >> 1, half = nf & 1;
      pa[kc][half * 2 + 0] = u01;
      pa[kc][half * 2 + 1] = u23;
    }
    rs0 += __shfl_xor_sync(0xffffffffu, rs0, 1);
    rs0 += __shfl_xor_sync(0xffffffffu, rs0, 2);
    rs1 += __shfl_xor_sync(0xffffffffu, rs1, 1);
    rs1 += __shfl_xor_sync(0xffffffffu, rs1, 2);
    l0 = l0 * al0 + rs0;
    l1 = l1 * al1 + rs1;
    m0 = mn0;
    m1 = mn1;
#pragma unroll
    for (int nf = 0; nf < 8; nf++) {
      O[nf][0] *= al0; O[nf][1] *= al0;
      O[nf][2] *= al1; O[nf][3] *= al1;
    }

    // ---- O += P @ V (single fp16 MMA; B = Vt fp16) ----
#pragma unroll
    for (int kc = 0; kc < 4; kc++) {
#pragma unroll
      for (int ng = 0; ng < 4; ng++) {
        uint32_t v4[4];
        ldmx4(v4, sVt + (ng * 16) * LDF + kc * 32 + b_off);
        mma_fp16(O[2 * ng], pa[kc], v4);
        mma_fp16(O[2 * ng + 1], pa[kc], v4 + 2);
      }
    }
    __syncthreads();
    if (kb + 2 <= qb) issue_kv(kb + 2, kb & 1);
  }

  // ---- epilogue: ctx ----
  const float i0 = 1.0f / l0, i1 = 1.0f / l1;
  float* Cg = g_ctx + ((size_t)(b * Sn + qb * 64)) * Dn + h * 64;
#pragma unroll
  for (int nf = 0; nf < 8; nf++) {
    int colb = nf * 8 + cq;
    *(float2*)(Cg + (size_t)(w * 16 + r0) * Dn + colb) =
        make_float2(O[nf][0] * i0, O[nf][1] * i0);
    *(float2*)(Cg + (size_t)(w * 16 + r0 + 8) * Dn + colb) =
        make_float2(O[nf][2] * i1, O[nf][3] * i1);
  }
  // ---- epilogue: final rescale factors for attn materialization ----
  if ((lane & 3) == 0) {
    const int rloc = w * 16 + r0;
    const size_t tri0 = (size_t)bh * NTRI + (size_t)(qb * (qb + 1) / 2);
    for (int kb = 0; kb <= qb; kb++) {
      g_mr[(tri0 + kb) * 64 + rloc] = __expf(smr[kb * 64 + rloc] - m0) * i0;
      g_mr[(tri0 + kb) * 64 + rloc + 8] =
          __expf(smr[kb * 64 + rloc + 8] - m1) * i1;
    }
  }
}

// ---------------------------------------------------------------------------
// Kernel 3: attn materialization (R13 structure): attn = P_fp16 * scale,
// scale precomputed by flash. grid = (32, 32, 64), 256 threads.
// ---------------------------------------------------------------------------
__global__ __launch_bounds__(256) void attn_write_fast(
    float* __restrict__ attn) {
  const int kb = blockIdx.x, qb = blockIdx.y, bh = blockIdx.z;
  const int t = threadIdx.x;
  const int row = t >> 2, c16 = (t & 3) << 4;
  float* dst = attn + ((size_t)bh * Sn + qb * 64 + row) * Sn +
               (size_t)kb * 64 + c16;

  if (kb > qb) {
    float4 z = make_float4(0.f, 0.f, 0.f, 0.f);
#pragma unroll
    for (int j = 0; j < 4; j++) __stcs((float4*)(dst + 4 * j), z);
    return;
  }

  const size_t tri = (size_t)bh * NTRI + (size_t)(qb * (qb + 1) / 2) + kb;
  const __half2* Pt =
      (const __half2*)(g_P + tri * 4096 + row * 64 + c16);
  const float scale = __ldca(g_mr + tri * 64 + row);
#pragma unroll
  for (int j = 0; j < 4; j++) {
    float2 p0 = __half22float2(Pt[2 * j]);
    float2 p1 = __half22float2(Pt[2 * j + 1]);
    __stcs((float4*)(dst + 4 * j),
           make_float4(p0.x * scale, p0.y * scale, p1.x * scale,
                       p1.y * scale));
  }
}

// ---------------------------------------------------------------------------
// Kernel 4: residual add + LayerNorm.  grid = 8192 rows, 256 threads.
// ---------------------------------------------------------------------------
__global__ __launch_bounds__(256) void ln_kernel(
    const float* __restrict__ res, const float* __restrict__ gamma,
    const float* __restrict__ beta, float* __restrict__ out) {
  const int row = blockIdx.x;
  const int t = threadIdx.x;
  const float4 cv = ((const float4*)(g_ctx + (size_t)row * Dn))[t];
  const float4 rv = ((const float4*)(res + (size_t)row * Dn))[t];
  float x0 = cv.x + rv.x, x1 = cv.y + rv.y, x2 = cv.z + rv.z, x3 = cv.w + rv.w;

  float sum = x0 + x1 + x2 + x3;
  float sq = x0 * x0 + x1 * x1 + x2 * x2 + x3 * x3;
#pragma unroll
  for (int off = 16; off > 0; off >>= 1) {
    sum += __shfl_xor_sync(0xffffffffu, sum, off);
    sq += __shfl_xor_sync(0xffffffffu, sq, off);
  }
  __shared__ float ssum[8], ssq[8];
  const int w = t >> 5, lane = t & 31;
  if (lane == 0) { ssum[w] = sum; ssq[w] = sq; }
  __syncthreads();
  if (w == 0) {
    float a = (lane < 8) ? ssum[lane] : 0.f;
    float b2 = (lane < 8) ? ssq[lane] : 0.f;
#pragma unroll
    for (int off = 4; off > 0; off >>= 1) {
      a += __shfl_xor_sync(0xffffffffu, a, off);
      b2 += __shfl_xor_sync(0xffffffffu, b2, off);
    }
    if (lane == 0) { ssum[0] = a; ssq[0] = b2; }
  }
  __syncthreads();
  const float mean = ssum[0] * (1.0f / 1024.0f);
  const float var = ssq[0] * (1.0f / 1024.0f) - mean * mean;
  const float rstd = rsqrtf(var + 1e-5f);

  const float4 g = ((const float4*)gamma)[t];
  const float4 be = ((const float4*)beta)[t];
  float4 o = make_float4((x0 - mean) * rstd * g.x + be.x,
                         (x1 - mean) * rstd * g.y + be.y,
                         (x2 - mean) * rstd * g.z + be.z,
                         (x3 - mean) * rstd * g.w + be.w);
  ((float4*)(out + (size_t)row * Dn))[t] = o;
}

// ---------------------------------------------------------------------------
// Inputs (metadata order): q, k, v, mask, Wq, Wk, Wv, ln_gamma, ln_beta
// Output: concat(out[B,S,D], attn[B,H,S,S]) as float32.
// ---------------------------------------------------------------------------
extern "C" void kernel_launch(void* const* d_in, const int* in_sizes, int n_in,
                              void* d_out, int out_size) {
  const float* q = (const float*)d_in[0];
  const float* k = (const float*)d_in[1];
  const float* v = (const float*)d_in[2];
  // d_in[3] = mask (int32) — causal tril, applied analytically
  const float* Wq = (const float*)d_in[4];
  const float* Wk = (const float*)d_in[5];
  const float* Wv = (const float*)d_in[6];
  const float* gamma = (const float*)d_in[7];
  const float* beta = (const float*)d_in[8];
  float* out = (float*)d_out;

  cudaFuncSetAttribute(proj_mma, cudaFuncAttributeMaxDynamicSharedMemorySize,
                       PROJ_SMEM);
  cudaFuncSetAttribute(flash_tc, cudaFuncAttributeMaxDynamicSharedMemorySize,
                       FLASH_SMEM);

  prep_inputs<<<dim3(5120, 3), 256>>>(q, k, v, Wq, Wk, Wv);
  proj_mma<<<dim3(8, 64, 3), 256, PROJ_SMEM>>>();
  flash_tc<<<dim3(32, 16, 4), 128, FLASH_SMEM>>>();
  if ((size_t)out_size >= OUT_ELEMS + ATTN_ELEMS) {
    attn_write_fast<<<dim3(32, 32, 64), 256>>>(out + OUT_ELEMS);
  }
  ln_kernel<<<Mn, 256>>>(q, gamma, beta, out);
}